// round 6
// baseline (speedup 1.0000x reference)
#include <cuda_runtime.h>
#include <cuda_bf16.h>

#define B_  4
#define S_  1024
#define H_  16
#define D_  64
#define E_  1024
#define P_  1024
#define NS_ 2048
#define K_  1024

__device__ float g_Qh[B_ * H_ * S_ * D_];     // Q in [B,H,S,D]
__device__ float g_attn[B_ * S_ * E_];        // attention out [B,S,E]

// ---------------- helpers ----------------
__device__ __forceinline__ unsigned f2tf32(float x) {
    unsigned r; asm("cvt.rna.tf32.f32 %0, %1;" : "=r"(r) : "f"(x)); return r;
}
__device__ __forceinline__ float ex2f(float x) {
    float r; asm("ex2.approx.ftz.f32 %0, %1;" : "=f"(r) : "f"(x)); return r;
}
__device__ __forceinline__ void mma_tf32(float* d, const unsigned* a, const unsigned* b) {
    asm volatile("mma.sync.aligned.m16n8k8.row.col.f32.tf32.tf32.f32 "
        "{%0,%1,%2,%3}, {%4,%5,%6,%7}, {%8,%9}, {%0,%1,%2,%3};"
        : "+f"(d[0]), "+f"(d[1]), "+f"(d[2]), "+f"(d[3])
        : "r"(a[0]), "r"(a[1]), "r"(a[2]), "r"(a[3]), "r"(b[0]), "r"(b[1]));
}

// ---------------- copy past -> present ----------------
__global__ __launch_bounds__(256) void copy_past_kernel(const float* __restrict__ past,
                                                        float* __restrict__ present)
{
    int blk = blockIdx.x;            // 512 blocks: cbh(128) x quarter(4)
    int cbh = blk >> 2, qtr = blk & 3;
    const float4* src = (const float4*)(past + (size_t)cbh * (P_ * D_) + qtr * (P_ * D_ / 4));
    float4* dst = (float4*)(present + (size_t)cbh * (NS_ * D_) + qtr * (P_ * D_ / 4));
    for (int i = threadIdx.x; i < (P_ * D_ / 4) / 4; i += 256)
        dst[i] = src[i];
}

// ---------------- tf32 GEMM: C[M=4096, N] = A[M,1024] @ B[1024,N] + bias ----
// 128 threads, 4 warps, 64x64 per warp. qkv_mode=1: route q/k/v; 0: A=g_attn.
__global__ __launch_bounds__(128) void gemm_tf32_kernel(
    const float* __restrict__ Ain, const float* __restrict__ Bw,
    const float* __restrict__ bias, float* __restrict__ Cout,
    float* __restrict__ present, int N, int qkv_mode)
{
    const float* A = qkv_mode ? Ain : (const float*)g_attn;

    __shared__ unsigned As[2][16][136];
    __shared__ unsigned Bs[2][16][136];

    int t = threadIdx.x;
    int bm = blockIdx.y * 128, bn = blockIdx.x * 128;
    int w = t >> 5, l = t & 31;
    int wm = (w & 1) * 64, wn = (w >> 1) * 64;
    int r = l >> 2, c = l & 3;

    // global load mapping
    int bkr = t >> 3, bc0 = (t & 7) * 4;    // B: k-row bkr, col groups bc0+32i

    float acc[4][8][4];
#pragma unroll
    for (int i = 0; i < 4; i++)
#pragma unroll
        for (int j = 0; j < 8; j++)
#pragma unroll
            for (int k = 0; k < 4; k++) acc[i][j][k] = 0.f;

    const float* Ap = A + (size_t)(bm + t) * K_;          // one row per thread
    const float* Bp = Bw + (size_t)bkr * N + bn + bc0;

    float4 pa[4], pb[4];
#pragma unroll
    for (int i = 0; i < 4; i++) {
        pa[i] = *(const float4*)(Ap + 4 * i);
        pb[i] = *(const float4*)(Bp + 32 * i);
    }

    int buf = 0;
    for (int k0 = 0; k0 < K_; k0 += 16) {
#pragma unroll
        for (int i = 0; i < 4; i++) {
            As[buf][4 * i + 0][t] = f2tf32(pa[i].x);
            As[buf][4 * i + 1][t] = f2tf32(pa[i].y);
            As[buf][4 * i + 2][t] = f2tf32(pa[i].z);
            As[buf][4 * i + 3][t] = f2tf32(pa[i].w);
            uint4 u = make_uint4(f2tf32(pb[i].x), f2tf32(pb[i].y),
                                 f2tf32(pb[i].z), f2tf32(pb[i].w));
            *(uint4*)&Bs[buf][bkr][bc0 + 32 * i] = u;
        }
        __syncthreads();

        if (k0 + 16 < K_) {
#pragma unroll
            for (int i = 0; i < 4; i++) {
                pa[i] = *(const float4*)(Ap + k0 + 16 + 4 * i);
                pb[i] = *(const float4*)(Bp + (size_t)(k0 + 16) * N + 32 * i);
            }
        }

#pragma unroll
        for (int kk = 0; kk < 16; kk += 8) {
            unsigned af[4][4], bf[8][2];
#pragma unroll
            for (int mi = 0; mi < 4; mi++) {
                int m0 = wm + mi * 16;
                af[mi][0] = As[buf][kk + c][m0 + r];
                af[mi][1] = As[buf][kk + c][m0 + r + 8];
                af[mi][2] = As[buf][kk + c + 4][m0 + r];
                af[mi][3] = As[buf][kk + c + 4][m0 + r + 8];
            }
#pragma unroll
            for (int ni = 0; ni < 8; ni++) {
                int n0 = wn + ni * 8;
                bf[ni][0] = Bs[buf][kk + c][n0 + r];
                bf[ni][1] = Bs[buf][kk + c + 4][n0 + r];
            }
#pragma unroll
            for (int mi = 0; mi < 4; mi++)
#pragma unroll
                for (int ni = 0; ni < 8; ni++)
                    mma_tf32(acc[mi][ni], af[mi], bf[ni]);
        }
        buf ^= 1;
        __syncthreads();
    }

    // epilogue
#pragma unroll
    for (int mi = 0; mi < 4; mi++) {
#pragma unroll
        for (int ni = 0; ni < 8; ni++) {
            int row0 = bm + wm + mi * 16 + r;
            int col = bn + wn + ni * 8 + 2 * c;
#pragma unroll
            for (int jj = 0; jj < 4; jj++) {
                int row = (jj < 2) ? row0 : row0 + 8;
                int cg = col + (jj & 1);
                float v = acc[mi][ni][jj] + bias[cg];
                if (!qkv_mode) {
                    Cout[(size_t)row * N + cg] = v;
                } else {
                    int b = row >> 10, s = row & 1023;
                    int part = cg >> 10, nn = cg & 1023;
                    int h = nn >> 6, d = nn & 63;
                    if (part == 0)
                        g_Qh[(((b * H_ + h) * S_) + s) * D_ + d] = v;
                    else if (part == 1)
                        present[(((size_t)(b * H_ + h)) * NS_ + P_ + s) * D_ + d] = v;
                    else
                        present[(((size_t)((B_ + b) * H_ + h)) * NS_ + P_ + s) * D_ + d] = v;
                }
            }
        }
    }
}

// ---------------- tensor-core flash attention (all-tf32) ----------------
// CTA: 128 q-rows x (b,h). 8 warps, warp w owns rows [16w,16w+16).
// scores: tf32 mma (Q regs x K smem). PV: tf32 mma, P repacked via shfl.
__global__ __launch_bounds__(256) void attn_mma_kernel(const float* __restrict__ present)
{
    __shared__ unsigned Ks[64][68];          // tf32 bits, [key][d]
    __shared__ unsigned Vt[64][68];          // tf32 bits, [d][key] transposed

    int t = threadIdx.x, w = t >> 5, l = t & 31;
    int r = l >> 2, c = l & 3;
    int bh = blockIdx.y, q0 = blockIdx.x * 128;
    int b = bh >> 4, h = bh & 15;

    const float* Kb = present + (size_t)bh * (NS_ * D_);
    const float* Vb = present + (size_t)(B_ * H_ + bh) * (NS_ * D_);

    // Q fragments, prescaled by 1/sqrt(64) * log2(e)
    const float SC = 0.125f * 1.4426950408889634f;
    unsigned qf[8][4];
    {
        const float* Qp = g_Qh + ((size_t)bh * S_ + q0 + w * 16) * D_;
#pragma unroll
        for (int ks = 0; ks < 8; ks++) {
            int kc = ks * 8;
            qf[ks][0] = f2tf32(SC * Qp[(size_t)r * D_ + kc + c]);
            qf[ks][1] = f2tf32(SC * Qp[(size_t)(r + 8) * D_ + kc + c]);
            qf[ks][2] = f2tf32(SC * Qp[(size_t)r * D_ + kc + c + 4]);
            qf[ks][3] = f2tf32(SC * Qp[(size_t)(r + 8) * D_ + kc + c + 4]);
        }
    }

    float o[8][4];
#pragma unroll
    for (int i = 0; i < 8; i++)
#pragma unroll
        for (int j = 0; j < 4; j++) o[i][j] = 0.f;
    const float NEG = __int_as_float(0xff800000);
    float m0 = NEG, m1 = NEG, l0 = 0.f, l1 = 0.f;

    int key = t >> 2, cb = (t & 3) * 4;      // staging: rows=key, col groups cb+16i
    float4 pk[4], pv[4];
#pragma unroll
    for (int i = 0; i < 4; i++) {
        pk[i] = *(const float4*)(Kb + (size_t)key * D_ + cb + 16 * i);
        pv[i] = *(const float4*)(Vb + (size_t)key * D_ + cb + 16 * i);
    }

    // shuffle source lanes for P repack (A-frag needs key-cols c and c+4)
    int lsrc0 = (l & ~3) | (c >> 1);
    int lsrc1 = lsrc0 + 2;
    bool sel = (c & 1);

    int ntiles = (P_ + q0 + 128) / 64;
    for (int it = 0; it < ntiles; ++it) {
        int j0 = it * 64;
        // stage tiles
#pragma unroll
        for (int i = 0; i < 4; i++) {
            int cc = cb + 16 * i;
            Ks[key][cc + 0] = f2tf32(pk[i].x);
            Ks[key][cc + 1] = f2tf32(pk[i].y);
            Ks[key][cc + 2] = f2tf32(pk[i].z);
            Ks[key][cc + 3] = f2tf32(pk[i].w);
            Vt[cc + 0][key] = f2tf32(pv[i].x);
            Vt[cc + 1][key] = f2tf32(pv[i].y);
            Vt[cc + 2][key] = f2tf32(pv[i].z);
            Vt[cc + 3][key] = f2tf32(pv[i].w);
        }
        __syncthreads();

        if (it + 1 < ntiles) {
            int jn = j0 + 64;
#pragma unroll
            for (int i = 0; i < 4; i++) {
                pk[i] = *(const float4*)(Kb + (size_t)(jn + key) * D_ + cb + 16 * i);
                pv[i] = *(const float4*)(Vb + (size_t)(jn + key) * D_ + cb + 16 * i);
            }
        }

        // scores: s[nt] = 16x8 tile over keys j0+8nt..+7
        float s[8][4];
#pragma unroll
        for (int nt = 0; nt < 8; nt++) {
            s[nt][0] = s[nt][1] = s[nt][2] = s[nt][3] = 0.f;
#pragma unroll
            for (int ks = 0; ks < 8; ks++) {
                unsigned bf[2] = { Ks[nt * 8 + r][ks * 8 + c], Ks[nt * 8 + r][ks * 8 + c + 4] };
                mma_tf32(s[nt], qf[ks], bf);
            }
        }

        // causal mask
        int qrow = q0 + w * 16 + r;
        int lim0 = P_ + qrow - j0;       // key col allowed iff <= lim
        int lim1 = lim0 + 8;
#pragma unroll
        for (int nt = 0; nt < 8; nt++) {
            int j = nt * 8 + 2 * c;
            if (j > lim0) s[nt][0] = NEG;
            if (j + 1 > lim0) s[nt][1] = NEG;
            if (j > lim1) s[nt][2] = NEG;
            if (j + 1 > lim1) s[nt][3] = NEG;
        }

        // online softmax (base-2 domain)
        float mx0 = NEG, mx1 = NEG;
#pragma unroll
        for (int nt = 0; nt < 8; nt++) {
            mx0 = fmaxf(mx0, fmaxf(s[nt][0], s[nt][1]));
            mx1 = fmaxf(mx1, fmaxf(s[nt][2], s[nt][3]));
        }
        mx0 = fmaxf(mx0, __shfl_xor_sync(0xffffffffu, mx0, 1));
        mx0 = fmaxf(mx0, __shfl_xor_sync(0xffffffffu, mx0, 2));
        mx1 = fmaxf(mx1, __shfl_xor_sync(0xffffffffu, mx1, 1));
        mx1 = fmaxf(mx1, __shfl_xor_sync(0xffffffffu, mx1, 2));
        float nm0 = fmaxf(m0, mx0), nm1 = fmaxf(m1, mx1);
        float a0 = ex2f(m0 - nm0), a1 = ex2f(m1 - nm1);
        m0 = nm0; m1 = nm1;
        l0 *= a0; l1 *= a1;
#pragma unroll
        for (int nt = 0; nt < 8; nt++) {
            s[nt][0] = ex2f(s[nt][0] - nm0);
            s[nt][1] = ex2f(s[nt][1] - nm0);
            s[nt][2] = ex2f(s[nt][2] - nm1);
            s[nt][3] = ex2f(s[nt][3] - nm1);
            l0 += s[nt][0] + s[nt][1];
            l1 += s[nt][2] + s[nt][3];
            o[nt][0] *= a0; o[nt][1] *= a0;
            o[nt][2] *= a1; o[nt][3] *= a1;
        }

        // PV: o += P(tf32) @ V(tf32); P fragment via in-warp shuffle repack
#pragma unroll
        for (int ks = 0; ks < 8; ks++) {
            unsigned p0 = f2tf32(s[ks][0]), p1 = f2tf32(s[ks][1]);
            unsigned p2 = f2tf32(s[ks][2]), p3 = f2tf32(s[ks][3]);
            unsigned u0 = __shfl_sync(0xffffffffu, p0, lsrc0);
            unsigned u1 = __shfl_sync(0xffffffffu, p1, lsrc0);
            unsigned u2 = __shfl_sync(0xffffffffu, p2, lsrc0);
            unsigned u3 = __shfl_sync(0xffffffffu, p3, lsrc0);
            unsigned v0 = __shfl_sync(0xffffffffu, p0, lsrc1);
            unsigned v1 = __shfl_sync(0xffffffffu, p1, lsrc1);
            unsigned v2 = __shfl_sync(0xffffffffu, p2, lsrc1);
            unsigned v3 = __shfl_sync(0xffffffffu, p3, lsrc1);
            unsigned ap[4];
            ap[0] = sel ? u1 : u0;       // P(r,   ks*8+c)
            ap[1] = sel ? u3 : u2;       // P(r+8, ks*8+c)
            ap[2] = sel ? v1 : v0;       // P(r,   ks*8+c+4)
            ap[3] = sel ? v3 : v2;       // P(r+8, ks*8+c+4)
#pragma unroll
            for (int nt = 0; nt < 8; nt++) {
                unsigned bf[2] = { Vt[nt * 8 + r][ks * 8 + c], Vt[nt * 8 + r][ks * 8 + c + 4] };
                mma_tf32(o[nt], ap, bf);
            }
        }
        __syncthreads();
    }

    // finalize
    l0 += __shfl_xor_sync(0xffffffffu, l0, 1);
    l0 += __shfl_xor_sync(0xffffffffu, l0, 2);
    l1 += __shfl_xor_sync(0xffffffffu, l1, 1);
    l1 += __shfl_xor_sync(0xffffffffu, l1, 2);
    float inv0 = 1.f / l0, inv1 = 1.f / l1;

    int qrow = q0 + w * 16 + r;
    float* dst0 = g_attn + ((size_t)(b * S_ + qrow)) * E_ + h * D_;
    float* dst1 = dst0 + (size_t)8 * E_;
#pragma unroll
    for (int nt = 0; nt < 8; nt++) {
        int cc = nt * 8 + 2 * c;
        *(float2*)(dst0 + cc) = make_float2(o[nt][0] * inv0, o[nt][1] * inv0);
        *(float2*)(dst1 + cc) = make_float2(o[nt][2] * inv1, o[nt][3] * inv1);
    }
}

// ---------------------------------------------------------------------------
extern "C" void kernel_launch(void* const* d_in, const int* in_sizes, int n_in,
                              void* d_out, int out_size)
{
    (void)in_sizes; (void)n_in; (void)out_size;
    const float* x      = (const float*)d_in[0];
    const float* past   = (const float*)d_in[1];
    const float* w_attn = (const float*)d_in[2];
    const float* b_attn = (const float*)d_in[3];
    const float* w_proj = (const float*)d_in[4];
    const float* b_proj = (const float*)d_in[5];

    float* out     = (float*)d_out;
    float* present = out + (size_t)B_ * S_ * E_;

    copy_past_kernel<<<512, 256>>>(past, present);
    gemm_tf32_kernel<<<dim3(3 * E_ / 128, (B_ * S_) / 128), 128>>>(
        x, w_attn, b_attn, nullptr, present, 3 * E_, 1);
    attn_mma_kernel<<<dim3(S_ / 128, B_ * H_), 256>>>(present);
    gemm_tf32_kernel<<<dim3(E_ / 128, (B_ * S_) / 128), 128>>>(
        nullptr, w_proj, b_proj, out, nullptr, E_, 0);
}

// round 8
// speedup vs baseline: 1.3053x; 1.3053x over previous
#include <cuda_runtime.h>
#include <cuda_fp16.h>

#define B_  4
#define S_  1024
#define H_  16
#define D_  64
#define E_  1024
#define P_  1024
#define NS_ 2048
#define K_  1024

__device__ float g_Qh[B_ * H_ * S_ * D_];     // Q in [B,H,S,D]
__device__ float g_attn[B_ * S_ * E_];        // attention out [B,S,E]

// ---------------- helpers ----------------
__device__ __forceinline__ unsigned f2tf32(float x) {
    unsigned r; asm("cvt.rna.tf32.f32 %0, %1;" : "=r"(r) : "f"(x)); return r;
}
__device__ __forceinline__ unsigned pack_f16(float lo, float hi) {
    unsigned r; asm("cvt.rn.f16x2.f32 %0, %1, %2;" : "=r"(r) : "f"(hi), "f"(lo)); return r;
}
__device__ __forceinline__ float ex2f(float x) {
    float r; asm("ex2.approx.ftz.f32 %0, %1;" : "=f"(r) : "f"(x)); return r;
}
__device__ __forceinline__ void mma_tf32(float* d, const unsigned* a, const unsigned* b) {
    asm volatile("mma.sync.aligned.m16n8k8.row.col.f32.tf32.tf32.f32 "
        "{%0,%1,%2,%3}, {%4,%5,%6,%7}, {%8,%9}, {%0,%1,%2,%3};"
        : "+f"(d[0]), "+f"(d[1]), "+f"(d[2]), "+f"(d[3])
        : "r"(a[0]), "r"(a[1]), "r"(a[2]), "r"(a[3]), "r"(b[0]), "r"(b[1]));
}
__device__ __forceinline__ void mma_f16(float* d, const unsigned* a, const unsigned* b) {
    asm volatile("mma.sync.aligned.m16n8k16.row.col.f32.f16.f16.f32 "
        "{%0,%1,%2,%3}, {%4,%5,%6,%7}, {%8,%9}, {%0,%1,%2,%3};"
        : "+f"(d[0]), "+f"(d[1]), "+f"(d[2]), "+f"(d[3])
        : "r"(a[0]), "r"(a[1]), "r"(a[2]), "r"(a[3]), "r"(b[0]), "r"(b[1]));
}

// ---------------- tf32 GEMM (R4 config: 256 thr, 8 warps, 64x32/warp) -------
// qkv_mode=1: route q->g_Qh, k/v->present, extra blocks copy past->present.
// qkv_mode=0: A = g_attn, plain store to Cout.
__global__ __launch_bounds__(256) void gemm_tf32_kernel(
    const float* __restrict__ Ain, const float* __restrict__ Bw,
    const float* __restrict__ bias, float* __restrict__ Cout,
    float* __restrict__ present, int N, int qkv_mode,
    const float* __restrict__ past)
{
    // ---- merged past-copy blocks (qkv launch adds 4 extra block columns) ----
    if (qkv_mode && (int)blockIdx.x >= (N >> 7)) {
        int part = ((int)blockIdx.x - (N >> 7)) * (int)gridDim.y + (int)blockIdx.y; // 0..127
        const float4* src = (const float4*)(past + (size_t)part * (P_ * D_));
        float4* dst = (float4*)(present + (size_t)part * (NS_ * D_));
#pragma unroll 4
        for (int i = threadIdx.x; i < (P_ * D_) / 4; i += 256)
            dst[i] = src[i];
        return;
    }

    const float* A = qkv_mode ? Ain : (const float*)g_attn;

    __shared__ unsigned As[2][16][136];
    __shared__ unsigned Bs[2][16][136];

    int t = threadIdx.x;
    int bm = blockIdx.y * 128, bn = blockIdx.x * 128;
    int w = t >> 5, l = t & 31;
    int wm = (w & 1) * 64, wn = (w >> 1) * 32;
    int r = l >> 2, c = l & 3;

    int ar = t >> 2, ac = (t & 3) * 4;      // A: rows ar, ar+64 ; k-cols ac..ac+3
    int bkr = t >> 4, bcg = (t & 15) * 4;   // B: k-row bkr ; cols bcg, bcg+64

    float acc[4][4][4];
#pragma unroll
    for (int i = 0; i < 4; i++)
#pragma unroll
        for (int j = 0; j < 4; j++)
#pragma unroll
            for (int k = 0; k < 4; k++) acc[i][j][k] = 0.f;

    const float* Ap = A + (size_t)(bm + ar) * K_ + ac;
    const float* Bp = Bw + (size_t)bkr * N + bn + bcg;

    float4 pa0 = *(const float4*)(Ap);
    float4 pa1 = *(const float4*)(Ap + (size_t)64 * K_);
    float4 pb0 = *(const float4*)(Bp);
    float4 pb1 = *(const float4*)(Bp + 64);

    int buf = 0;
    for (int k0 = 0; k0 < K_; k0 += 16) {
        As[buf][ac + 0][ar] = f2tf32(pa0.x);
        As[buf][ac + 1][ar] = f2tf32(pa0.y);
        As[buf][ac + 2][ar] = f2tf32(pa0.z);
        As[buf][ac + 3][ar] = f2tf32(pa0.w);
        As[buf][ac + 0][ar + 64] = f2tf32(pa1.x);
        As[buf][ac + 1][ar + 64] = f2tf32(pa1.y);
        As[buf][ac + 2][ar + 64] = f2tf32(pa1.z);
        As[buf][ac + 3][ar + 64] = f2tf32(pa1.w);
        {
            uint4 u0 = make_uint4(f2tf32(pb0.x), f2tf32(pb0.y), f2tf32(pb0.z), f2tf32(pb0.w));
            uint4 u1 = make_uint4(f2tf32(pb1.x), f2tf32(pb1.y), f2tf32(pb1.z), f2tf32(pb1.w));
            *(uint4*)&Bs[buf][bkr][bcg] = u0;
            *(uint4*)&Bs[buf][bkr][bcg + 64] = u1;
        }
        __syncthreads();

        if (k0 + 16 < K_) {
            pa0 = *(const float4*)(Ap + k0 + 16);
            pa1 = *(const float4*)(Ap + (size_t)64 * K_ + k0 + 16);
            pb0 = *(const float4*)(Bp + (size_t)(k0 + 16) * N);
            pb1 = *(const float4*)(Bp + (size_t)(k0 + 16) * N + 64);
        }

#pragma unroll
        for (int kk = 0; kk < 16; kk += 8) {
            unsigned af[4][4], bf[4][2];
#pragma unroll
            for (int mi = 0; mi < 4; mi++) {
                int m0 = wm + mi * 16;
                af[mi][0] = As[buf][kk + c][m0 + r];
                af[mi][1] = As[buf][kk + c][m0 + r + 8];
                af[mi][2] = As[buf][kk + c + 4][m0 + r];
                af[mi][3] = As[buf][kk + c + 4][m0 + r + 8];
            }
#pragma unroll
            for (int ni = 0; ni < 4; ni++) {
                int n0 = wn + ni * 8;
                bf[ni][0] = Bs[buf][kk + c][n0 + r];
                bf[ni][1] = Bs[buf][kk + c + 4][n0 + r];
            }
#pragma unroll
            for (int mi = 0; mi < 4; mi++)
#pragma unroll
                for (int ni = 0; ni < 4; ni++)
                    mma_tf32(acc[mi][ni], af[mi], bf[ni]);
        }
        buf ^= 1;
        __syncthreads();
    }

    // epilogue
#pragma unroll
    for (int mi = 0; mi < 4; mi++) {
#pragma unroll
        for (int ni = 0; ni < 4; ni++) {
            int row0 = bm + wm + mi * 16 + r;
            int col = bn + wn + ni * 8 + 2 * c;
#pragma unroll
            for (int jj = 0; jj < 4; jj++) {
                int row = (jj < 2) ? row0 : row0 + 8;
                int cg = col + (jj & 1);
                float v = acc[mi][ni][jj] + bias[cg];
                if (!qkv_mode) {
                    Cout[(size_t)row * N + cg] = v;
                } else {
                    int b = row >> 10, s = row & 1023;
                    int part = cg >> 10, nn = cg & 1023;
                    int h = nn >> 6, d = nn & 63;
                    if (part == 0)
                        g_Qh[(((b * H_ + h) * S_) + s) * D_ + d] = v;
                    else if (part == 1)
                        present[(((size_t)(b * H_ + h)) * NS_ + P_ + s) * D_ + d] = v;
                    else
                        present[(((size_t)((B_ + b) * H_ + h)) * NS_ + P_ + s) * D_ + d] = v;
                }
            }
        }
    }
}

// ---------------- fp16 tensor-core flash attention ----------------
// CTA: 128 q-rows x (b,h). 8 warps, warp w owns rows [16w,16w+16).
// scores: f16 m16n8k16 (Q regs x K smem). PV: f16 m16n8k16 (P pack x V^T smem).
// Double-buffered smem, one __syncthreads per 64-key tile.
__global__ __launch_bounds__(256) void attn_mma_kernel(const float* __restrict__ present)
{
    __shared__ __align__(16) __half Ks[2][64][72];   // [key][d]
    __shared__ __align__(16) __half Vt[2][64][72];   // [d][key] transposed

    int t = threadIdx.x, w = t >> 5, l = t & 31;
    int r = l >> 2, c = l & 3;
    int bh = blockIdx.y, q0 = blockIdx.x * 128;
    int b = bh >> 4, h = bh & 15;

    const float* Kb = present + (size_t)bh * (NS_ * D_);
    const float* Vb = present + (size_t)(B_ * H_ + bh) * (NS_ * D_);

    // Q fragments (f16), prescaled by 1/sqrt(64) * log2(e)
    const float SC = 0.125f * 1.4426950408889634f;
    unsigned qf[4][4];
    {
        const float* Qp = g_Qh + ((size_t)bh * S_ + q0 + w * 16) * D_;
#pragma unroll
        for (int kc = 0; kc < 4; kc++) {
            int base = kc * 16;
            qf[kc][0] = pack_f16(SC * Qp[(size_t)r * D_ + base + 2 * c],
                                 SC * Qp[(size_t)r * D_ + base + 2 * c + 1]);
            qf[kc][1] = pack_f16(SC * Qp[(size_t)(r + 8) * D_ + base + 2 * c],
                                 SC * Qp[(size_t)(r + 8) * D_ + base + 2 * c + 1]);
            qf[kc][2] = pack_f16(SC * Qp[(size_t)r * D_ + base + 8 + 2 * c],
                                 SC * Qp[(size_t)r * D_ + base + 8 + 2 * c + 1]);
            qf[kc][3] = pack_f16(SC * Qp[(size_t)(r + 8) * D_ + base + 8 + 2 * c],
                                 SC * Qp[(size_t)(r + 8) * D_ + base + 8 + 2 * c + 1]);
        }
    }

    float o[8][4];
#pragma unroll
    for (int i = 0; i < 8; i++)
#pragma unroll
        for (int j = 0; j < 4; j++) o[i][j] = 0.f;
    const float NEG = __int_as_float(0xff800000);
    float m0 = NEG, m1 = NEG, l0 = 0.f, l1 = 0.f;

    int key = t >> 2, cb = (t & 3) * 4;      // staging: row=key, col groups cb+16i
    float4 pk[4], pv[4];
#pragma unroll
    for (int i = 0; i < 4; i++) {
        pk[i] = *(const float4*)(Kb + (size_t)key * D_ + cb + 16 * i);
        pv[i] = *(const float4*)(Vb + (size_t)key * D_ + cb + 16 * i);
    }
    // stage tile 0 into buffer 0
#pragma unroll
    for (int i = 0; i < 4; i++) {
        int cc = cb + 16 * i;
        *(__half2*)&Ks[0][key][cc]     = __floats2half2_rn(pk[i].x, pk[i].y);
        *(__half2*)&Ks[0][key][cc + 2] = __floats2half2_rn(pk[i].z, pk[i].w);
        Vt[0][cc + 0][key] = __float2half_rn(pv[i].x);
        Vt[0][cc + 1][key] = __float2half_rn(pv[i].y);
        Vt[0][cc + 2][key] = __float2half_rn(pv[i].z);
        Vt[0][cc + 3][key] = __float2half_rn(pv[i].w);
    }
    __syncthreads();

    int ntiles = (P_ + q0 + 128) / 64;
    for (int it = 0; it < ntiles; ++it) {
        int buf = it & 1;
        bool more = (it + 1 < ntiles);
        if (more) {
            int jn = (it + 1) * 64;
#pragma unroll
            for (int i = 0; i < 4; i++) {
                pk[i] = *(const float4*)(Kb + (size_t)(jn + key) * D_ + cb + 16 * i);
                pv[i] = *(const float4*)(Vb + (size_t)(jn + key) * D_ + cb + 16 * i);
            }
        }

        // scores: s[nt] = 16x8 tile over keys it*64+8nt..+7
        float s[8][4];
#pragma unroll
        for (int nt = 0; nt < 8; nt++)
            s[nt][0] = s[nt][1] = s[nt][2] = s[nt][3] = 0.f;
#pragma unroll
        for (int kc = 0; kc < 4; kc++) {
#pragma unroll
            for (int nt = 0; nt < 8; nt++) {
                unsigned bf[2] = {
                    *(const unsigned*)&Ks[buf][nt * 8 + r][kc * 16 + 2 * c],
                    *(const unsigned*)&Ks[buf][nt * 8 + r][kc * 16 + 8 + 2 * c]
                };
                mma_f16(s[nt], qf[kc], bf);
            }
        }

        // stage next tile into other buffer (overlaps with softmax/PV)
        if (more) {
#pragma unroll
            for (int i = 0; i < 4; i++) {
                int cc = cb + 16 * i;
                *(__half2*)&Ks[buf ^ 1][key][cc]     = __floats2half2_rn(pk[i].x, pk[i].y);
                *(__half2*)&Ks[buf ^ 1][key][cc + 2] = __floats2half2_rn(pk[i].z, pk[i].w);
                Vt[buf ^ 1][cc + 0][key] = __float2half_rn(pv[i].x);
                Vt[buf ^ 1][cc + 1][key] = __float2half_rn(pv[i].y);
                Vt[buf ^ 1][cc + 2][key] = __float2half_rn(pv[i].z);
                Vt[buf ^ 1][cc + 3][key] = __float2half_rn(pv[i].w);
            }
        }

        // causal mask
        int j0 = it * 64;
        int qrow = q0 + w * 16 + r;
        int lim0 = P_ + qrow - j0;       // key col allowed iff <= lim
        int lim1 = lim0 + 8;
#pragma unroll
        for (int nt = 0; nt < 8; nt++) {
            int j = nt * 8 + 2 * c;
            if (j > lim0) s[nt][0] = NEG;
            if (j + 1 > lim0) s[nt][1] = NEG;
            if (j > lim1) s[nt][2] = NEG;
            if (j + 1 > lim1) s[nt][3] = NEG;
        }

        // online softmax (base-2 domain)
        float mx0 = NEG, mx1 = NEG;
#pragma unroll
        for (int nt = 0; nt < 8; nt++) {
            mx0 = fmaxf(mx0, fmaxf(s[nt][0], s[nt][1]));
            mx1 = fmaxf(mx1, fmaxf(s[nt][2], s[nt][3]));
        }
        mx0 = fmaxf(mx0, __shfl_xor_sync(0xffffffffu, mx0, 1));
        mx0 = fmaxf(mx0, __shfl_xor_sync(0xffffffffu, mx0, 2));
        mx1 = fmaxf(mx1, __shfl_xor_sync(0xffffffffu, mx1, 1));
        mx1 = fmaxf(mx1, __shfl_xor_sync(0xffffffffu, mx1, 2));
        float nm0 = fmaxf(m0, mx0), nm1 = fmaxf(m1, mx1);
        float a0 = ex2f(m0 - nm0), a1 = ex2f(m1 - nm1);
        m0 = nm0; m1 = nm1;
        l0 *= a0; l1 *= a1;
#pragma unroll
        for (int nt = 0; nt < 8; nt++) {
            s[nt][0] = ex2f(s[nt][0] - nm0);
            s[nt][1] = ex2f(s[nt][1] - nm0);
            s[nt][2] = ex2f(s[nt][2] - nm1);
            s[nt][3] = ex2f(s[nt][3] - nm1);
            l0 += s[nt][0] + s[nt][1];
            l1 += s[nt][2] + s[nt][3];
            o[nt][0] *= a0; o[nt][1] *= a0;
            o[nt][2] *= a1; o[nt][3] *= a1;
        }

        // PV: o += P(f16) @ V(f16), C-frag -> A-frag by direct f16x2 pack
#pragma unroll
        for (int ks = 0; ks < 4; ks++) {
            unsigned ap[4];
            ap[0] = pack_f16(s[2 * ks][0], s[2 * ks][1]);
            ap[1] = pack_f16(s[2 * ks][2], s[2 * ks][3]);
            ap[2] = pack_f16(s[2 * ks + 1][0], s[2 * ks + 1][1]);
            ap[3] = pack_f16(s[2 * ks + 1][2], s[2 * ks + 1][3]);
#pragma unroll
            for (int nt = 0; nt < 8; nt++) {
                unsigned bf[2] = {
                    *(const unsigned*)&Vt[buf][nt * 8 + r][ks * 16 + 2 * c],
                    *(const unsigned*)&Vt[buf][nt * 8 + r][ks * 16 + 8 + 2 * c]
                };
                mma_f16(o[nt], ap, bf);
            }
        }
        __syncthreads();
    }

    // finalize
    l0 += __shfl_xor_sync(0xffffffffu, l0, 1);
    l0 += __shfl_xor_sync(0xffffffffu, l0, 2);
    l1 += __shfl_xor_sync(0xffffffffu, l1, 1);
    l1 += __shfl_xor_sync(0xffffffffu, l1, 2);
    float inv0 = 1.f / l0, inv1 = 1.f / l1;

    int qrow = q0 + w * 16 + r;
    float* dst0 = g_attn + ((size_t)(b * S_ + qrow)) * E_ + h * D_;
    float* dst1 = dst0 + (size_t)8 * E_;
#pragma unroll
    for (int nt = 0; nt < 8; nt++) {
        int cc = nt * 8 + 2 * c;
        *(float2*)(dst0 + cc) = make_float2(o[nt][0] * inv0, o[nt][1] * inv0);
        *(float2*)(dst1 + cc) = make_float2(o[nt][2] * inv1, o[nt][3] * inv1);
    }
}

// ---------------------------------------------------------------------------
extern "C" void kernel_launch(void* const* d_in, const int* in_sizes, int n_in,
                              void* d_out, int out_size)
{
    (void)in_sizes; (void)n_in; (void)out_size;
    const float* x      = (const float*)d_in[0];
    const float* past   = (const float*)d_in[1];
    const float* w_attn = (const float*)d_in[2];
    const float* b_attn = (const float*)d_in[3];
    const float* w_proj = (const float*)d_in[4];
    const float* b_proj = (const float*)d_in[5];

    float* out     = (float*)d_out;
    float* present = out + (size_t)B_ * S_ * E_;

    // QKV GEMM + merged past->present copy (extra 4 block columns)
    gemm_tf32_kernel<<<dim3(3 * E_ / 128 + 4, (B_ * S_) / 128), 256>>>(
        x, w_attn, b_attn, nullptr, present, 3 * E_, 1, past);
    attn_mma_kernel<<<dim3(S_ / 128, B_ * H_), 256>>>(present);
    gemm_tf32_kernel<<<dim3(E_ / 128, (B_ * S_) / 128), 256>>>(
        nullptr, w_proj, b_proj, out, nullptr, E_, 0, nullptr);
}

// round 10
// speedup vs baseline: 1.8266x; 1.3993x over previous
#include <cuda_runtime.h>
#include <cuda_fp16.h>

#define B_  4
#define S_  1024
#define H_  16
#define D_  64
#define E_  1024
#define P_  1024
#define NS_ 2048
#define K_  1024

__device__ float g_Qh[B_ * H_ * S_ * D_];     // Q in [B,H,S,D]
__device__ float g_attn[B_ * S_ * E_];        // attention out [B,S,E]

// ---------------- helpers ----------------
__device__ __forceinline__ unsigned pack_f16(float lo, float hi) {
    unsigned r; asm("cvt.rn.f16x2.f32 %0, %1, %2;" : "=r"(r) : "f"(hi), "f"(lo)); return r;
}
__device__ __forceinline__ float ex2f(float x) {
    float r; asm("ex2.approx.ftz.f32 %0, %1;" : "=f"(r) : "f"(x)); return r;
}
__device__ __forceinline__ void mma_f16(float* d, const unsigned* a, const unsigned* b) {
    asm volatile("mma.sync.aligned.m16n8k16.row.col.f32.f16.f16.f32 "
        "{%0,%1,%2,%3}, {%4,%5,%6,%7}, {%8,%9}, {%0,%1,%2,%3};"
        : "+f"(d[0]), "+f"(d[1]), "+f"(d[2]), "+f"(d[3])
        : "r"(a[0]), "r"(a[1]), "r"(a[2]), "r"(a[3]), "r"(b[0]), "r"(b[1]));
}

// ---------------- f16 GEMM: C[M=4096, N] = A[M,1024] @ B[1024,N] + bias -----
// 256 thr, 8 warps, 64x32 per warp tile, double-buffered 16-k stages.
// Smem holds f16 pairs packed along k: As[kpair][m], Bs[kpair][n].
// qkv_mode=1: route q->g_Qh, k/v->present, extra blocks copy past->present.
// qkv_mode=0: A = g_attn, plain store to Cout.
__global__ __launch_bounds__(256) void gemm_f16_kernel(
    const float* __restrict__ Ain, const float* __restrict__ Bw,
    const float* __restrict__ bias, float* __restrict__ Cout,
    float* __restrict__ present, int N, int qkv_mode,
    const float* __restrict__ past)
{
    // ---- merged past-copy blocks (qkv launch adds 4 extra block columns) ----
    if (qkv_mode && (int)blockIdx.x >= (N >> 7)) {
        int part = ((int)blockIdx.x - (N >> 7)) * (int)gridDim.y + (int)blockIdx.y; // 0..127
        const float4* src = (const float4*)(past + (size_t)part * (P_ * D_));
        float4* dst = (float4*)(present + (size_t)part * (NS_ * D_));
#pragma unroll 4
        for (int i = threadIdx.x; i < (P_ * D_) / 4; i += 256)
            dst[i] = src[i];
        return;
    }

    const float* A = qkv_mode ? Ain : (const float*)g_attn;

    __shared__ unsigned As[2][8][136];   // [kpair][m] f16x2 (lo = even k)
    __shared__ unsigned Bs[2][8][136];   // [kpair][n] f16x2 (lo = even k)

    int t = threadIdx.x;
    int bm = blockIdx.y * 128, bn = blockIdx.x * 128;
    int w = t >> 5, l = t & 31;
    int wm = (w & 1) * 64, wn = (w >> 1) * 32;
    int r = l >> 2, c = l & 3;

    int ar = t >> 2, ac = (t & 3) * 4, akp = (t & 3) * 2;  // A: rows ar, ar+64
    int bj = t >> 5, bc = (t & 31) * 4;                    // B: kpair bj, n cols bc..+3

    float acc[4][4][4];
#pragma unroll
    for (int i = 0; i < 4; i++)
#pragma unroll
        for (int j = 0; j < 4; j++)
#pragma unroll
            for (int k = 0; k < 4; k++) acc[i][j][k] = 0.f;

    const float* Ap = A + (size_t)(bm + ar) * K_ + ac;
    const float* Bp = Bw + (size_t)(2 * bj) * N + bn + bc;

    float4 pa0 = *(const float4*)(Ap);
    float4 pa1 = *(const float4*)(Ap + (size_t)64 * K_);
    float4 pb0 = *(const float4*)(Bp);
    float4 pb1 = *(const float4*)(Bp + N);

    int buf = 0;
    for (int k0 = 0; k0 < K_; k0 += 16) {
        As[buf][akp + 0][ar]      = pack_f16(pa0.x, pa0.y);
        As[buf][akp + 1][ar]      = pack_f16(pa0.z, pa0.w);
        As[buf][akp + 0][ar + 64] = pack_f16(pa1.x, pa1.y);
        As[buf][akp + 1][ar + 64] = pack_f16(pa1.z, pa1.w);
        {
            uint4 u = make_uint4(pack_f16(pb0.x, pb1.x), pack_f16(pb0.y, pb1.y),
                                 pack_f16(pb0.z, pb1.z), pack_f16(pb0.w, pb1.w));
            *(uint4*)&Bs[buf][bj][bc] = u;
        }
        __syncthreads();

        if (k0 + 16 < K_) {
            pa0 = *(const float4*)(Ap + k0 + 16);
            pa1 = *(const float4*)(Ap + (size_t)64 * K_ + k0 + 16);
            pb0 = *(const float4*)(Bp + (size_t)(k0 + 16) * N);
            pb1 = *(const float4*)(Bp + (size_t)(k0 + 17) * N);
        }

        // one m16n8k16 pass over the staged 16 k
        {
            unsigned af[4][4], bf[4][2];
#pragma unroll
            for (int mi = 0; mi < 4; mi++) {
                int m0 = wm + mi * 16;
                af[mi][0] = As[buf][c][m0 + r];
                af[mi][1] = As[buf][c][m0 + r + 8];
                af[mi][2] = As[buf][4 + c][m0 + r];
                af[mi][3] = As[buf][4 + c][m0 + r + 8];
            }
#pragma unroll
            for (int ni = 0; ni < 4; ni++) {
                int n0 = wn + ni * 8;
                bf[ni][0] = Bs[buf][c][n0 + r];
                bf[ni][1] = Bs[buf][4 + c][n0 + r];
            }
#pragma unroll
            for (int mi = 0; mi < 4; mi++)
#pragma unroll
                for (int ni = 0; ni < 4; ni++)
                    mma_f16(acc[mi][ni], af[mi], bf[ni]);
        }
        buf ^= 1;
        __syncthreads();
    }

    // epilogue
#pragma unroll
    for (int mi = 0; mi < 4; mi++) {
#pragma unroll
        for (int ni = 0; ni < 4; ni++) {
            int row0 = bm + wm + mi * 16 + r;
            int col = bn + wn + ni * 8 + 2 * c;
#pragma unroll
            for (int jj = 0; jj < 4; jj++) {
                int row = (jj < 2) ? row0 : row0 + 8;
                int cg = col + (jj & 1);
                float v = acc[mi][ni][jj] + bias[cg];
                if (!qkv_mode) {
                    Cout[(size_t)row * N + cg] = v;
                } else {
                    int b = row >> 10, s = row & 1023;
                    int part = cg >> 10, nn = cg & 1023;
                    int h = nn >> 6, d = nn & 63;
                    if (part == 0)
                        g_Qh[(((b * H_ + h) * S_) + s) * D_ + d] = v;
                    else if (part == 1)
                        present[(((size_t)(b * H_ + h)) * NS_ + P_ + s) * D_ + d] = v;
                    else
                        present[(((size_t)((B_ + b) * H_ + h)) * NS_ + P_ + s) * D_ + d] = v;
                }
            }
        }
    }
}

// ---------------- fp16 tensor-core flash attention (unchanged from R8) ------
__global__ __launch_bounds__(256) void attn_mma_kernel(const float* __restrict__ present)
{
    __shared__ __align__(16) __half Ks[2][64][72];   // [key][d]
    __shared__ __align__(16) __half Vt[2][64][72];   // [d][key] transposed

    int t = threadIdx.x, w = t >> 5, l = t & 31;
    int r = l >> 2, c = l & 3;
    int bh = blockIdx.y, q0 = blockIdx.x * 128;
    int b = bh >> 4, h = bh & 15;

    const float* Kb = present + (size_t)bh * (NS_ * D_);
    const float* Vb = present + (size_t)(B_ * H_ + bh) * (NS_ * D_);

    const float SC = 0.125f * 1.4426950408889634f;
    unsigned qf[4][4];
    {
        const float* Qp = g_Qh + ((size_t)bh * S_ + q0 + w * 16) * D_;
#pragma unroll
        for (int kc = 0; kc < 4; kc++) {
            int base = kc * 16;
            qf[kc][0] = pack_f16(SC * Qp[(size_t)r * D_ + base + 2 * c],
                                 SC * Qp[(size_t)r * D_ + base + 2 * c + 1]);
            qf[kc][1] = pack_f16(SC * Qp[(size_t)(r + 8) * D_ + base + 2 * c],
                                 SC * Qp[(size_t)(r + 8) * D_ + base + 2 * c + 1]);
            qf[kc][2] = pack_f16(SC * Qp[(size_t)r * D_ + base + 8 + 2 * c],
                                 SC * Qp[(size_t)r * D_ + base + 8 + 2 * c + 1]);
            qf[kc][3] = pack_f16(SC * Qp[(size_t)(r + 8) * D_ + base + 8 + 2 * c],
                                 SC * Qp[(size_t)(r + 8) * D_ + base + 8 + 2 * c + 1]);
        }
    }

    float o[8][4];
#pragma unroll
    for (int i = 0; i < 8; i++)
#pragma unroll
        for (int j = 0; j < 4; j++) o[i][j] = 0.f;
    const float NEG = __int_as_float(0xff800000);
    float m0 = NEG, m1 = NEG, l0 = 0.f, l1 = 0.f;

    int key = t >> 2, cb = (t & 3) * 4;
    float4 pk[4], pv[4];
#pragma unroll
    for (int i = 0; i < 4; i++) {
        pk[i] = *(const float4*)(Kb + (size_t)key * D_ + cb + 16 * i);
        pv[i] = *(const float4*)(Vb + (size_t)key * D_ + cb + 16 * i);
    }
#pragma unroll
    for (int i = 0; i < 4; i++) {
        int cc = cb + 16 * i;
        *(__half2*)&Ks[0][key][cc]     = __floats2half2_rn(pk[i].x, pk[i].y);
        *(__half2*)&Ks[0][key][cc + 2] = __floats2half2_rn(pk[i].z, pk[i].w);
        Vt[0][cc + 0][key] = __float2half_rn(pv[i].x);
        Vt[0][cc + 1][key] = __float2half_rn(pv[i].y);
        Vt[0][cc + 2][key] = __float2half_rn(pv[i].z);
        Vt[0][cc + 3][key] = __float2half_rn(pv[i].w);
    }
    __syncthreads();

    int ntiles = (P_ + q0 + 128) / 64;
    for (int it = 0; it < ntiles; ++it) {
        int buf = it & 1;
        bool more = (it + 1 < ntiles);
        if (more) {
            int jn = (it + 1) * 64;
#pragma unroll
            for (int i = 0; i < 4; i++) {
                pk[i] = *(const float4*)(Kb + (size_t)(jn + key) * D_ + cb + 16 * i);
                pv[i] = *(const float4*)(Vb + (size_t)(jn + key) * D_ + cb + 16 * i);
            }
        }

        float s[8][4];
#pragma unroll
        for (int nt = 0; nt < 8; nt++)
            s[nt][0] = s[nt][1] = s[nt][2] = s[nt][3] = 0.f;
#pragma unroll
        for (int kc = 0; kc < 4; kc++) {
#pragma unroll
            for (int nt = 0; nt < 8; nt++) {
                unsigned bf[2] = {
                    *(const unsigned*)&Ks[buf][nt * 8 + r][kc * 16 + 2 * c],
                    *(const unsigned*)&Ks[buf][nt * 8 + r][kc * 16 + 8 + 2 * c]
                };
                mma_f16(s[nt], qf[kc], bf);
            }
        }

        if (more) {
#pragma unroll
            for (int i = 0; i < 4; i++) {
                int cc = cb + 16 * i;
                *(__half2*)&Ks[buf ^ 1][key][cc]     = __floats2half2_rn(pk[i].x, pk[i].y);
                *(__half2*)&Ks[buf ^ 1][key][cc + 2] = __floats2half2_rn(pk[i].z, pk[i].w);
                Vt[buf ^ 1][cc + 0][key] = __float2half_rn(pv[i].x);
                Vt[buf ^ 1][cc + 1][key] = __float2half_rn(pv[i].y);
                Vt[buf ^ 1][cc + 2][key] = __float2half_rn(pv[i].z);
                Vt[buf ^ 1][cc + 3][key] = __float2half_rn(pv[i].w);
            }
        }

        int j0 = it * 64;
        int qrow = q0 + w * 16 + r;
        int lim0 = P_ + qrow - j0;
        int lim1 = lim0 + 8;
#pragma unroll
        for (int nt = 0; nt < 8; nt++) {
            int j = nt * 8 + 2 * c;
            if (j > lim0) s[nt][0] = NEG;
            if (j + 1 > lim0) s[nt][1] = NEG;
            if (j > lim1) s[nt][2] = NEG;
            if (j + 1 > lim1) s[nt][3] = NEG;
        }

        float mx0 = NEG, mx1 = NEG;
#pragma unroll
        for (int nt = 0; nt < 8; nt++) {
            mx0 = fmaxf(mx0, fmaxf(s[nt][0], s[nt][1]));
            mx1 = fmaxf(mx1, fmaxf(s[nt][2], s[nt][3]));
        }
        mx0 = fmaxf(mx0, __shfl_xor_sync(0xffffffffu, mx0, 1));
        mx0 = fmaxf(mx0, __shfl_xor_sync(0xffffffffu, mx0, 2));
        mx1 = fmaxf(mx1, __shfl_xor_sync(0xffffffffu, mx1, 1));
        mx1 = fmaxf(mx1, __shfl_xor_sync(0xffffffffu, mx1, 2));
        float nm0 = fmaxf(m0, mx0), nm1 = fmaxf(m1, mx1);
        float a0 = ex2f(m0 - nm0), a1 = ex2f(m1 - nm1);
        m0 = nm0; m1 = nm1;
        l0 *= a0; l1 *= a1;
#pragma unroll
        for (int nt = 0; nt < 8; nt++) {
            s[nt][0] = ex2f(s[nt][0] - nm0);
            s[nt][1] = ex2f(s[nt][1] - nm0);
            s[nt][2] = ex2f(s[nt][2] - nm1);
            s[nt][3] = ex2f(s[nt][3] - nm1);
            l0 += s[nt][0] + s[nt][1];
            l1 += s[nt][2] + s[nt][3];
            o[nt][0] *= a0; o[nt][1] *= a0;
            o[nt][2] *= a1; o[nt][3] *= a1;
        }

#pragma unroll
        for (int ks = 0; ks < 4; ks++) {
            unsigned ap[4];
            ap[0] = pack_f16(s[2 * ks][0], s[2 * ks][1]);
            ap[1] = pack_f16(s[2 * ks][2], s[2 * ks][3]);
            ap[2] = pack_f16(s[2 * ks + 1][0], s[2 * ks + 1][1]);
            ap[3] = pack_f16(s[2 * ks + 1][2], s[2 * ks + 1][3]);
#pragma unroll
            for (int nt = 0; nt < 8; nt++) {
                unsigned bf[2] = {
                    *(const unsigned*)&Vt[buf][nt * 8 + r][ks * 16 + 2 * c],
                    *(const unsigned*)&Vt[buf][nt * 8 + r][ks * 16 + 8 + 2 * c]
                };
                mma_f16(o[nt], ap, bf);
            }
        }
        __syncthreads();
    }

    l0 += __shfl_xor_sync(0xffffffffu, l0, 1);
    l0 += __shfl_xor_sync(0xffffffffu, l0, 2);
    l1 += __shfl_xor_sync(0xffffffffu, l1, 1);
    l1 += __shfl_xor_sync(0xffffffffu, l1, 2);
    float inv0 = 1.f / l0, inv1 = 1.f / l1;

    int qrow = q0 + w * 16 + r;
    float* dst0 = g_attn + ((size_t)(b * S_ + qrow)) * E_ + h * D_;
    float* dst1 = dst0 + (size_t)8 * E_;
#pragma unroll
    for (int nt = 0; nt < 8; nt++) {
        int cc = nt * 8 + 2 * c;
        *(float2*)(dst0 + cc) = make_float2(o[nt][0] * inv0, o[nt][1] * inv0);
        *(float2*)(dst1 + cc) = make_float2(o[nt][2] * inv1, o[nt][3] * inv1);
    }
}

// ---------------------------------------------------------------------------
extern "C" void kernel_launch(void* const* d_in, const int* in_sizes, int n_in,
                              void* d_out, int out_size)
{
    (void)in_sizes; (void)n_in; (void)out_size;
    const float* x      = (const float*)d_in[0];
    const float* past   = (const float*)d_in[1];
    const float* w_attn = (const float*)d_in[2];
    const float* b_attn = (const float*)d_in[3];
    const float* w_proj = (const float*)d_in[4];
    const float* b_proj = (const float*)d_in[5];

    float* out     = (float*)d_out;
    float* present = out + (size_t)B_ * S_ * E_;

    gemm_f16_kernel<<<dim3(3 * E_ / 128 + 4, (B_ * S_) / 128), 256>>>(
        x, w_attn, b_attn, nullptr, present, 3 * E_, 1, past);
    attn_mma_kernel<<<dim3(S_ / 128, B_ * H_), 256>>>(present);
    gemm_f16_kernel<<<dim3(E_ / 128, (B_ * S_) / 128), 256>>>(
        nullptr, w_proj, b_proj, out, nullptr, E_, 0, nullptr);
}

// round 11
// speedup vs baseline: 1.8589x; 1.0177x over previous
#include <cuda_runtime.h>
#include <cuda_fp16.h>

#define B_  4
#define S_  1024
#define H_  16
#define D_  64
#define E_  1024
#define P_  1024
#define NS_ 2048
#define K_  1024

__device__ __align__(16) __half g_x16[B_ * S_ * E_];
__device__ __align__(16) __half g_wa16[E_ * 3 * E_];
__device__ __align__(16) __half g_wp16[E_ * E_];
__device__ __align__(16) __half g_Qh16[B_ * H_ * S_ * D_];   // Q [B,H,S,D] f16
__device__ __align__(16) __half g_attn16[B_ * S_ * E_];      // attn out f16

// ---------------- helpers ----------------
__device__ __forceinline__ unsigned pack_f16(float lo, float hi) {
    unsigned r; asm("cvt.rn.f16x2.f32 %0, %1, %2;" : "=r"(r) : "f"(hi), "f"(lo)); return r;
}
__device__ __forceinline__ float ex2f(float x) {
    float r; asm("ex2.approx.ftz.f32 %0, %1;" : "=f"(r) : "f"(x)); return r;
}
__device__ __forceinline__ void mma_f16(float* d, const unsigned* a, const unsigned* b) {
    asm volatile("mma.sync.aligned.m16n8k16.row.col.f32.f16.f16.f32 "
        "{%0,%1,%2,%3}, {%4,%5,%6,%7}, {%8,%9}, {%0,%1,%2,%3};"
        : "+f"(d[0]), "+f"(d[1]), "+f"(d[2]), "+f"(d[3])
        : "r"(a[0]), "r"(a[1]), "r"(a[2]), "r"(a[3]), "r"(b[0]), "r"(b[1]));
}
__device__ __forceinline__ unsigned su(const void* p) {
    return (unsigned)__cvta_generic_to_shared(p);
}
__device__ __forceinline__ void cp16(unsigned s, const void* g) {
    asm volatile("cp.async.ca.shared.global [%0], [%1], 16;" :: "r"(s), "l"(g));
}
__device__ __forceinline__ void cp_commit() {
    asm volatile("cp.async.commit_group;" ::: "memory");
}
template <int N> __device__ __forceinline__ void cp_wait() {
    asm volatile("cp.async.wait_group %0;" :: "n"(N) : "memory");
}
__device__ __forceinline__ void ldsm_x4_trans(unsigned* d, unsigned addr) {
    asm volatile("ldmatrix.sync.aligned.m8n8.x4.trans.shared.b16 {%0,%1,%2,%3}, [%4];"
        : "=r"(d[0]), "=r"(d[1]), "=r"(d[2]), "=r"(d[3]) : "r"(addr));
}

// ---------------- f32 -> f16 conversion (x, w_attn, w_proj) ----------------
__global__ __launch_bounds__(256) void convert_kernel(const float* __restrict__ x,
                                                      const float* __restrict__ wa,
                                                      const float* __restrict__ wp)
{
    const int NX4 = (B_ * S_ * E_) / 4;
    const int NWA4 = (E_ * 3 * E_) / 4;
    const int NWP4 = (E_ * E_) / 4;
    int gs = gridDim.x * blockDim.x;
    for (int i = blockIdx.x * blockDim.x + threadIdx.x; i < NX4 + NWA4 + NWP4; i += gs) {
        const float4* s; unsigned* d;
        if (i < NX4) { s = (const float4*)x + i; d = (unsigned*)g_x16 + i * 2; }
        else if (i < NX4 + NWA4) { int j = i - NX4; s = (const float4*)wa + j; d = (unsigned*)g_wa16 + j * 2; }
        else { int j = i - NX4 - NWA4; s = (const float4*)wp + j; d = (unsigned*)g_wp16 + j * 2; }
        float4 v = *s;
        d[0] = pack_f16(v.x, v.y);
        d[1] = pack_f16(v.z, v.w);
    }
}

// ---------------- pipelined f16 GEMM -----------------------------------------
// C[4096, N] = A[4096,1024] @ B[1024,N] + bias. 256 thr, 8 warps 64x32.
// 4-stage cp.async pipeline, k16 stages, 1 syncthreads per stage.
// qkv_mode=1: A=g_x16,B=g_wa16, q->g_Qh16(f16), k/v->present(f32), extra blocks copy past.
// qkv_mode=0: A=g_attn16, B=g_wp16, store f32 Cout.
#define AROW 24    // halfwords per A smem row (16 data + 8 pad = 48B)
#define BROW 136   // halfwords per B smem row (128 data + 8 pad = 272B)
__global__ __launch_bounds__(256) void gemm_f16_kernel(
    const float* __restrict__ bias, float* __restrict__ Cout,
    float* __restrict__ present, int N, int qkv_mode,
    const float* __restrict__ past)
{
    if (qkv_mode && (int)blockIdx.x >= (N >> 7)) {
        int part = ((int)blockIdx.x - (N >> 7)) * (int)gridDim.y + (int)blockIdx.y; // 0..127
        const float4* src = (const float4*)(past + (size_t)part * (P_ * D_));
        float4* dst = (float4*)(present + (size_t)part * (NS_ * D_));
#pragma unroll 4
        for (int i = threadIdx.x; i < (P_ * D_) / 4; i += 256)
            dst[i] = src[i];
        return;
    }

    const __half* A = qkv_mode ? g_x16 : g_attn16;
    const __half* Bw = qkv_mode ? g_wa16 : g_wp16;

    __shared__ __align__(16) __half As[4][128 * AROW];
    __shared__ __align__(16) __half Bs[4][16 * BROW];

    int t = threadIdx.x;
    int bm = blockIdx.y * 128, bn = blockIdx.x * 128;
    int w = t >> 5, l = t & 31;
    int wm = (w & 1) * 64, wn = (w >> 1) * 32;
    int r = l >> 2, c = l & 3;

    float acc[4][4][4];
#pragma unroll
    for (int i = 0; i < 4; i++)
#pragma unroll
        for (int j = 0; j < 4; j++)
#pragma unroll
            for (int k = 0; k < 4; k++) acc[i][j][k] = 0.f;

    // per-thread staging slots (one 16B A chunk + one 16B B chunk per stage)
    int a_row = t >> 1, a_off = (t & 1) * 8;          // A: 128 rows x 2 chunks
    int b_row = t >> 4, b_off = (t & 15) * 8;         // B: 16 rows x 16 chunks
    const __half* Ag = A + (size_t)(bm + a_row) * K_ + a_off;
    const __half* Bg = Bw + (size_t)b_row * N + bn + b_off;

    // ldmatrix B address (per-lane): row = l&15, nhalf = (l>>4)*8
    int lm_k = l & 15, lm_n = wn + (l >> 4) * 8;

    // prologue: stages 0,1,2
#pragma unroll
    for (int p = 0; p < 3; p++) {
        cp16(su(&As[p][a_row * AROW + a_off]), Ag + p * 16);
        cp16(su(&Bs[p][b_row * BROW + b_off]), Bg + (size_t)(p * 16) * N);
        cp_commit();
    }

    const int NIT = K_ / 16;   // 64
    for (int it = 0; it < NIT; ++it) {
        int buf = it & 3;
        cp_wait<2>();
        __syncthreads();

        if (it + 3 < NIT) {
            int nb = (it + 3) & 3, k0 = (it + 3) * 16;
            cp16(su(&As[nb][a_row * AROW + a_off]), Ag + k0);
            cp16(su(&Bs[nb][b_row * BROW + b_off]), Bg + (size_t)k0 * N);
        }
        cp_commit();

        // fragments
        unsigned af[4][4];
#pragma unroll
        for (int mi = 0; mi < 4; mi++) {
            int hw = (wm + mi * 16 + r) * AROW + 2 * c;
            af[mi][0] = *(const unsigned*)&As[buf][hw];
            af[mi][1] = *(const unsigned*)&As[buf][hw + 8 * AROW];
            af[mi][2] = *(const unsigned*)&As[buf][hw + 8];
            af[mi][3] = *(const unsigned*)&As[buf][hw + 8 * AROW + 8];
        }
        unsigned bf[2][4];
        ldsm_x4_trans(bf[0], su(&Bs[buf][lm_k * BROW + lm_n]));
        ldsm_x4_trans(bf[1], su(&Bs[buf][lm_k * BROW + lm_n + 16]));

#pragma unroll
        for (int mi = 0; mi < 4; mi++)
#pragma unroll
            for (int ni = 0; ni < 4; ni++)
                mma_f16(acc[mi][ni], af[mi], &bf[ni >> 1][(ni & 1) * 2]);
    }

    // epilogue
#pragma unroll
    for (int mi = 0; mi < 4; mi++) {
#pragma unroll
        for (int ni = 0; ni < 4; ni++) {
            int row0 = bm + wm + mi * 16 + r;
            int col = bn + wn + ni * 8 + 2 * c;
#pragma unroll
            for (int half = 0; half < 2; half++) {     // half=0: rows r, half=1: r+8
                int row = row0 + half * 8;
                float v0 = acc[mi][ni][half * 2 + 0] + bias[col];
                float v1 = acc[mi][ni][half * 2 + 1] + bias[col + 1];
                if (!qkv_mode) {
                    *(float2*)&Cout[(size_t)row * N + col] = make_float2(v0, v1);
                } else {
                    int b = row >> 10, s = row & 1023;
                    int part = col >> 10, nn = col & 1023;
                    int h = nn >> 6, d = nn & 63;
                    if (part == 0) {
                        *(unsigned*)&g_Qh16[(((size_t)(b * H_ + h) * S_) + s) * D_ + d] =
                            pack_f16(v0, v1);
                    } else if (part == 1) {
                        *(float2*)&present[(((size_t)(b * H_ + h)) * NS_ + P_ + s) * D_ + d] =
                            make_float2(v0, v1);
                    } else {
                        *(float2*)&present[(((size_t)((B_ + b) * H_ + h)) * NS_ + P_ + s) * D_ + d] =
                            make_float2(v0, v1);
                    }
                }
            }
        }
    }
}

// ---------------- fp16 tensor-core flash attention ----------------
__global__ __launch_bounds__(256) void attn_mma_kernel(const float* __restrict__ present)
{
    __shared__ __align__(16) __half Ks[2][64][72];   // [key][d]
    __shared__ __align__(16) __half Vt[2][64][72];   // [d][key] transposed

    int t = threadIdx.x, w = t >> 5, l = t & 31;
    int r = l >> 2, c = l & 3;
    int bh = blockIdx.y, q0 = blockIdx.x * 128;
    int b = bh >> 4, h = bh & 15;

    const float* Kb = present + (size_t)bh * (NS_ * D_);
    const float* Vb = present + (size_t)(B_ * H_ + bh) * (NS_ * D_);

    // Q fragments: direct packed f16 loads (raw; scale applied to scores)
    const float SC = 0.125f * 1.4426950408889634f;
    unsigned qf[4][4];
    {
        const __half* Qp = g_Qh16 + ((size_t)bh * S_ + q0 + w * 16) * D_;
#pragma unroll
        for (int kc = 0; kc < 4; kc++) {
            int base = kc * 16;
            qf[kc][0] = *(const unsigned*)(Qp + (size_t)r * D_ + base + 2 * c);
            qf[kc][1] = *(const unsigned*)(Qp + (size_t)(r + 8) * D_ + base + 2 * c);
            qf[kc][2] = *(const unsigned*)(Qp + (size_t)r * D_ + base + 8 + 2 * c);
            qf[kc][3] = *(const unsigned*)(Qp + (size_t)(r + 8) * D_ + base + 8 + 2 * c);
        }
    }

    float o[8][4];
#pragma unroll
    for (int i = 0; i < 8; i++)
#pragma unroll
        for (int j = 0; j < 4; j++) o[i][j] = 0.f;
    const float NEG = __int_as_float(0xff800000);
    float m0 = NEG, m1 = NEG, l0 = 0.f, l1 = 0.f;

    int key = t >> 2, cb = (t & 3) * 4;
    float4 pk[4], pv[4];
#pragma unroll
    for (int i = 0; i < 4; i++) {
        pk[i] = *(const float4*)(Kb + (size_t)key * D_ + cb + 16 * i);
        pv[i] = *(const float4*)(Vb + (size_t)key * D_ + cb + 16 * i);
    }
#pragma unroll
    for (int i = 0; i < 4; i++) {
        int cc = cb + 16 * i;
        *(__half2*)&Ks[0][key][cc]     = __floats2half2_rn(pk[i].x, pk[i].y);
        *(__half2*)&Ks[0][key][cc + 2] = __floats2half2_rn(pk[i].z, pk[i].w);
        Vt[0][cc + 0][key] = __float2half_rn(pv[i].x);
        Vt[0][cc + 1][key] = __float2half_rn(pv[i].y);
        Vt[0][cc + 2][key] = __float2half_rn(pv[i].z);
        Vt[0][cc + 3][key] = __float2half_rn(pv[i].w);
    }
    __syncthreads();

    int ntiles = (P_ + q0 + 128) / 64;
    for (int it = 0; it < ntiles; ++it) {
        int buf = it & 1;
        bool more = (it + 1 < ntiles);
        if (more) {
            int jn = (it + 1) * 64;
#pragma unroll
            for (int i = 0; i < 4; i++) {
                pk[i] = *(const float4*)(Kb + (size_t)(jn + key) * D_ + cb + 16 * i);
                pv[i] = *(const float4*)(Vb + (size_t)(jn + key) * D_ + cb + 16 * i);
            }
        }

        float s[8][4];
#pragma unroll
        for (int nt = 0; nt < 8; nt++)
            s[nt][0] = s[nt][1] = s[nt][2] = s[nt][3] = 0.f;
#pragma unroll
        for (int kc = 0; kc < 4; kc++) {
#pragma unroll
            for (int nt = 0; nt < 8; nt++) {
                unsigned bf[2] = {
                    *(const unsigned*)&Ks[buf][nt * 8 + r][kc * 16 + 2 * c],
                    *(const unsigned*)&Ks[buf][nt * 8 + r][kc * 16 + 8 + 2 * c]
                };
                mma_f16(s[nt], qf[kc], bf);
            }
        }
        // apply softmax scale (in f32, post-mma)
#pragma unroll
        for (int nt = 0; nt < 8; nt++) {
            s[nt][0] *= SC; s[nt][1] *= SC; s[nt][2] *= SC; s[nt][3] *= SC;
        }

        if (more) {
#pragma unroll
            for (int i = 0; i < 4; i++) {
                int cc = cb + 16 * i;
                *(__half2*)&Ks[buf ^ 1][key][cc]     = __floats2half2_rn(pk[i].x, pk[i].y);
                *(__half2*)&Ks[buf ^ 1][key][cc + 2] = __floats2half2_rn(pk[i].z, pk[i].w);
                Vt[buf ^ 1][cc + 0][key] = __float2half_rn(pv[i].x);
                Vt[buf ^ 1][cc + 1][key] = __float2half_rn(pv[i].y);
                Vt[buf ^ 1][cc + 2][key] = __float2half_rn(pv[i].z);
                Vt[buf ^ 1][cc + 3][key] = __float2half_rn(pv[i].w);
            }
        }

        int j0 = it * 64;
        int qrow = q0 + w * 16 + r;
        int lim0 = P_ + qrow - j0;
        int lim1 = lim0 + 8;
#pragma unroll
        for (int nt = 0; nt < 8; nt++) {
            int j = nt * 8 + 2 * c;
            if (j > lim0) s[nt][0] = NEG;
            if (j + 1 > lim0) s[nt][1] = NEG;
            if (j > lim1) s[nt][2] = NEG;
            if (j + 1 > lim1) s[nt][3] = NEG;
        }

        float mx0 = NEG, mx1 = NEG;
#pragma unroll
        for (int nt = 0; nt < 8; nt++) {
            mx0 = fmaxf(mx0, fmaxf(s[nt][0], s[nt][1]));
            mx1 = fmaxf(mx1, fmaxf(s[nt][2], s[nt][3]));
        }
        mx0 = fmaxf(mx0, __shfl_xor_sync(0xffffffffu, mx0, 1));
        mx0 = fmaxf(mx0, __shfl_xor_sync(0xffffffffu, mx0, 2));
        mx1 = fmaxf(mx1, __shfl_xor_sync(0xffffffffu, mx1, 1));
        mx1 = fmaxf(mx1, __shfl_xor_sync(0xffffffffu, mx1, 2));
        float nm0 = fmaxf(m0, mx0), nm1 = fmaxf(m1, mx1);
        float a0 = ex2f(m0 - nm0), a1 = ex2f(m1 - nm1);
        m0 = nm0; m1 = nm1;
        l0 *= a0; l1 *= a1;
#pragma unroll
        for (int nt = 0; nt < 8; nt++) {
            s[nt][0] = ex2f(s[nt][0] - nm0);
            s[nt][1] = ex2f(s[nt][1] - nm0);
            s[nt][2] = ex2f(s[nt][2] - nm1);
            s[nt][3] = ex2f(s[nt][3] - nm1);
            l0 += s[nt][0] + s[nt][1];
            l1 += s[nt][2] + s[nt][3];
            o[nt][0] *= a0; o[nt][1] *= a0;
            o[nt][2] *= a1; o[nt][3] *= a1;
        }

#pragma unroll
        for (int ks = 0; ks < 4; ks++) {
            unsigned ap[4];
            ap[0] = pack_f16(s[2 * ks][0], s[2 * ks][1]);
            ap[1] = pack_f16(s[2 * ks][2], s[2 * ks][3]);
            ap[2] = pack_f16(s[2 * ks + 1][0], s[2 * ks + 1][1]);
            ap[3] = pack_f16(s[2 * ks + 1][2], s[2 * ks + 1][3]);
#pragma unroll
            for (int nt = 0; nt < 8; nt++) {
                unsigned bf[2] = {
                    *(const unsigned*)&Vt[buf][nt * 8 + r][ks * 16 + 2 * c],
                    *(const unsigned*)&Vt[buf][nt * 8 + r][ks * 16 + 8 + 2 * c]
                };
                mma_f16(o[nt], ap, bf);
            }
        }
        __syncthreads();
    }

    l0 += __shfl_xor_sync(0xffffffffu, l0, 1);
    l0 += __shfl_xor_sync(0xffffffffu, l0, 2);
    l1 += __shfl_xor_sync(0xffffffffu, l1, 1);
    l1 += __shfl_xor_sync(0xffffffffu, l1, 2);
    float inv0 = 1.f / l0, inv1 = 1.f / l1;

    int qrow = q0 + w * 16 + r;
    __half* dst0 = g_attn16 + ((size_t)(b * S_ + qrow)) * E_ + h * D_;
    __half* dst1 = dst0 + (size_t)8 * E_;
#pragma unroll
    for (int nt = 0; nt < 8; nt++) {
        int cc = nt * 8 + 2 * c;
        *(unsigned*)(dst0 + cc) = pack_f16(o[nt][0] * inv0, o[nt][1] * inv0);
        *(unsigned*)(dst1 + cc) = pack_f16(o[nt][2] * inv1, o[nt][3] * inv1);
    }
}

// ---------------------------------------------------------------------------
extern "C" void kernel_launch(void* const* d_in, const int* in_sizes, int n_in,
                              void* d_out, int out_size)
{
    (void)in_sizes; (void)n_in; (void)out_size;
    const float* x      = (const float*)d_in[0];
    const float* past   = (const float*)d_in[1];
    const float* b_attn = (const float*)d_in[3];
    const float* w_attn = (const float*)d_in[2];
    const float* w_proj = (const float*)d_in[4];
    const float* b_proj = (const float*)d_in[5];

    float* out     = (float*)d_out;
    float* present = out + (size_t)B_ * S_ * E_;

    convert_kernel<<<1024, 256>>>(x, w_attn, w_proj);
    gemm_f16_kernel<<<dim3(3 * E_ / 128 + 4, (B_ * S_) / 128), 256>>>(
        b_attn, nullptr, present, 3 * E_, 1, past);
    attn_mma_kernel<<<dim3(S_ / 128, B_ * H_), 256>>>(present);
    gemm_f16_kernel<<<dim3(E_ / 128, (B_ * S_) / 128), 256>>>(
        b_proj, out, nullptr, E_, 0, nullptr);
}

// round 12
// speedup vs baseline: 2.2673x; 1.2197x over previous
#include <cuda_runtime.h>
#include <cuda_fp16.h>

#define B_  4
#define S_  1024
#define H_  16
#define D_  64
#define E_  1024
#define P_  1024
#define NS_ 2048
#define K_  1024

__device__ __align__(16) __half g_x16[B_ * S_ * E_];
__device__ __align__(16) __half g_wa16[E_ * 3 * E_];
__device__ __align__(16) __half g_wp16[E_ * E_];
__device__ __align__(16) __half g_Qh16[B_ * H_ * S_ * D_];     // Q [B,H,S,D] f16
__device__ __align__(16) __half g_attn16[B_ * S_ * E_];        // attn out f16
__device__ __align__(16) __half g_kv16[2 * B_ * H_ * NS_ * D_]; // f16 mirror of present

// ---------------- helpers ----------------
__device__ __forceinline__ unsigned pack_f16(float lo, float hi) {
    unsigned r; asm("cvt.rn.f16x2.f32 %0, %1, %2;" : "=r"(r) : "f"(hi), "f"(lo)); return r;
}
__device__ __forceinline__ float ex2f(float x) {
    float r; asm("ex2.approx.ftz.f32 %0, %1;" : "=f"(r) : "f"(x)); return r;
}
__device__ __forceinline__ unsigned h2exp(unsigned x) {
    unsigned r; asm("ex2.approx.f16x2 %0, %1;" : "=r"(r) : "r"(x)); return r;
}
__device__ __forceinline__ void mma_f16(float* d, const unsigned* a, const unsigned* b) {
    asm volatile("mma.sync.aligned.m16n8k16.row.col.f32.f16.f16.f32 "
        "{%0,%1,%2,%3}, {%4,%5,%6,%7}, {%8,%9}, {%0,%1,%2,%3};"
        : "+f"(d[0]), "+f"(d[1]), "+f"(d[2]), "+f"(d[3])
        : "r"(a[0]), "r"(a[1]), "r"(a[2]), "r"(a[3]), "r"(b[0]), "r"(b[1]));
}
__device__ __forceinline__ unsigned su(const void* p) {
    return (unsigned)__cvta_generic_to_shared(p);
}
__device__ __forceinline__ void cp16(unsigned s, const void* g) {
    asm volatile("cp.async.ca.shared.global [%0], [%1], 16;" :: "r"(s), "l"(g));
}
__device__ __forceinline__ void cp_commit() {
    asm volatile("cp.async.commit_group;" ::: "memory");
}
template <int N> __device__ __forceinline__ void cp_wait() {
    asm volatile("cp.async.wait_group %0;" :: "n"(N) : "memory");
}
__device__ __forceinline__ void ldsm_x4_trans(unsigned* d, unsigned addr) {
    asm volatile("ldmatrix.sync.aligned.m8n8.x4.trans.shared.b16 {%0,%1,%2,%3}, [%4];"
        : "=r"(d[0]), "=r"(d[1]), "=r"(d[2]), "=r"(d[3]) : "r"(addr));
}

// ---------------- f32 -> f16 conversion (x, w_attn, w_proj) ----------------
__global__ __launch_bounds__(256) void convert_kernel(const float* __restrict__ x,
                                                      const float* __restrict__ wa,
                                                      const float* __restrict__ wp)
{
    const int NX4 = (B_ * S_ * E_) / 4;
    const int NWA4 = (E_ * 3 * E_) / 4;
    const int NWP4 = (E_ * E_) / 4;
    int gs = gridDim.x * blockDim.x;
    for (int i = blockIdx.x * blockDim.x + threadIdx.x; i < NX4 + NWA4 + NWP4; i += gs) {
        const float4* s; unsigned* d;
        if (i < NX4) { s = (const float4*)x + i; d = (unsigned*)g_x16 + i * 2; }
        else if (i < NX4 + NWA4) { int j = i - NX4; s = (const float4*)wa + j; d = (unsigned*)g_wa16 + j * 2; }
        else { int j = i - NX4 - NWA4; s = (const float4*)wp + j; d = (unsigned*)g_wp16 + j * 2; }
        float4 v = *s;
        d[0] = pack_f16(v.x, v.y);
        d[1] = pack_f16(v.z, v.w);
    }
}

// ---------------- pipelined f16 GEMM -----------------------------------------
#define AROW 24    // halfwords per A smem row (16 data + 8 pad = 48B)
#define BROW 136   // halfwords per B smem row (128 data + 8 pad = 272B)
__global__ __launch_bounds__(256) void gemm_f16_kernel(
    const float* __restrict__ bias, float* __restrict__ Cout,
    float* __restrict__ present, int N, int qkv_mode,
    const float* __restrict__ past)
{
    if (qkv_mode && (int)blockIdx.x >= (N >> 7)) {
        int part = ((int)blockIdx.x - (N >> 7)) * (int)gridDim.y + (int)blockIdx.y; // 0..127
        const float4* src = (const float4*)(past + (size_t)part * (P_ * D_));
        float4* dst = (float4*)(present + (size_t)part * (NS_ * D_));
        uint2* dst16 = (uint2*)(g_kv16 + (size_t)part * (NS_ * D_));
#pragma unroll 4
        for (int i = threadIdx.x; i < (P_ * D_) / 4; i += 256) {
            float4 v = src[i];
            dst[i] = v;
            dst16[i] = make_uint2(pack_f16(v.x, v.y), pack_f16(v.z, v.w));
        }
        return;
    }

    const __half* A = qkv_mode ? g_x16 : g_attn16;
    const __half* Bw = qkv_mode ? g_wa16 : g_wp16;

    __shared__ __align__(16) __half As[4][128 * AROW];
    __shared__ __align__(16) __half Bs[4][16 * BROW];

    int t = threadIdx.x;
    int bm = blockIdx.y * 128, bn = blockIdx.x * 128;
    int w = t >> 5, l = t & 31;
    int wm = (w & 1) * 64, wn = (w >> 1) * 32;
    int r = l >> 2, c = l & 3;

    float acc[4][4][4];
#pragma unroll
    for (int i = 0; i < 4; i++)
#pragma unroll
        for (int j = 0; j < 4; j++)
#pragma unroll
            for (int k = 0; k < 4; k++) acc[i][j][k] = 0.f;

    int a_row = t >> 1, a_off = (t & 1) * 8;
    int b_row = t >> 4, b_off = (t & 15) * 8;
    const __half* Ag = A + (size_t)(bm + a_row) * K_ + a_off;
    const __half* Bg = Bw + (size_t)b_row * N + bn + b_off;

    int lm_k = l & 15, lm_n = wn + (l >> 4) * 8;

#pragma unroll
    for (int p = 0; p < 3; p++) {
        cp16(su(&As[p][a_row * AROW + a_off]), Ag + p * 16);
        cp16(su(&Bs[p][b_row * BROW + b_off]), Bg + (size_t)(p * 16) * N);
        cp_commit();
    }

    const int NIT = K_ / 16;   // 64
    for (int it = 0; it < NIT; ++it) {
        int buf = it & 3;
        cp_wait<2>();
        __syncthreads();

        if (it + 3 < NIT) {
            int nb = (it + 3) & 3, k0 = (it + 3) * 16;
            cp16(su(&As[nb][a_row * AROW + a_off]), Ag + k0);
            cp16(su(&Bs[nb][b_row * BROW + b_off]), Bg + (size_t)k0 * N);
        }
        cp_commit();

        unsigned af[4][4];
#pragma unroll
        for (int mi = 0; mi < 4; mi++) {
            int hw = (wm + mi * 16 + r) * AROW + 2 * c;
            af[mi][0] = *(const unsigned*)&As[buf][hw];
            af[mi][1] = *(const unsigned*)&As[buf][hw + 8 * AROW];
            af[mi][2] = *(const unsigned*)&As[buf][hw + 8];
            af[mi][3] = *(const unsigned*)&As[buf][hw + 8 * AROW + 8];
        }
        unsigned bf[2][4];
        ldsm_x4_trans(bf[0], su(&Bs[buf][lm_k * BROW + lm_n]));
        ldsm_x4_trans(bf[1], su(&Bs[buf][lm_k * BROW + lm_n + 16]));

#pragma unroll
        for (int mi = 0; mi < 4; mi++)
#pragma unroll
            for (int ni = 0; ni < 4; ni++)
                mma_f16(acc[mi][ni], af[mi], &bf[ni >> 1][(ni & 1) * 2]);
    }

    // epilogue
#pragma unroll
    for (int mi = 0; mi < 4; mi++) {
#pragma unroll
        for (int ni = 0; ni < 4; ni++) {
            int row0 = bm + wm + mi * 16 + r;
            int col = bn + wn + ni * 8 + 2 * c;
#pragma unroll
            for (int half = 0; half < 2; half++) {
                int row = row0 + half * 8;
                float v0 = acc[mi][ni][half * 2 + 0] + bias[col];
                float v1 = acc[mi][ni][half * 2 + 1] + bias[col + 1];
                if (!qkv_mode) {
                    *(float2*)&Cout[(size_t)row * N + col] = make_float2(v0, v1);
                } else {
                    int b = row >> 10, s = row & 1023;
                    int part = col >> 10, nn = col & 1023;
                    int h = nn >> 6, d = nn & 63;
                    if (part == 0) {
                        *(unsigned*)&g_Qh16[(((size_t)(b * H_ + h) * S_) + s) * D_ + d] =
                            pack_f16(v0, v1);
                    } else {
                        int cbh = (part == 1) ? (b * H_ + h) : ((B_ + b) * H_ + h);
                        size_t idx = ((size_t)cbh * NS_ + P_ + s) * D_ + d;
                        *(float2*)&present[idx] = make_float2(v0, v1);
                        *(unsigned*)&g_kv16[idx] = pack_f16(v0, v1);
                    }
                }
            }
        }
    }
}

// ---------------- fp16 flash attention: cp.async KV, ldsm V, f16x2 ex2 ------
#define KVROW 72   // halfwords per smem row (64 data + 8 pad = 144B)
__global__ __launch_bounds__(256) void attn_mma_kernel()
{
    __shared__ __align__(16) __half Ks[2][64][KVROW];
    __shared__ __align__(16) __half Vs[2][64][KVROW];

    int t = threadIdx.x, w = t >> 5, l = t & 31;
    int r = l >> 2, c = l & 3;
    int bh = blockIdx.y, q0 = blockIdx.x * 128;
    int b = bh >> 4, h = bh & 15;

    const __half* Kb = g_kv16 + (size_t)bh * (NS_ * D_);
    const __half* Vb = g_kv16 + (size_t)(B_ * H_ + bh) * (NS_ * D_);

    const float SC = 0.125f * 1.4426950408889634f;
    unsigned qf[4][4];
    {
        const __half* Qp = g_Qh16 + ((size_t)bh * S_ + q0 + w * 16) * D_;
#pragma unroll
        for (int kc = 0; kc < 4; kc++) {
            int base = kc * 16;
            qf[kc][0] = *(const unsigned*)(Qp + (size_t)r * D_ + base + 2 * c);
            qf[kc][1] = *(const unsigned*)(Qp + (size_t)(r + 8) * D_ + base + 2 * c);
            qf[kc][2] = *(const unsigned*)(Qp + (size_t)r * D_ + base + 8 + 2 * c);
            qf[kc][3] = *(const unsigned*)(Qp + (size_t)(r + 8) * D_ + base + 8 + 2 * c);
        }
    }

    float o[8][4];
#pragma unroll
    for (int i = 0; i < 8; i++)
#pragma unroll
        for (int j = 0; j < 4; j++) o[i][j] = 0.f;
    const float NEG = __int_as_float(0xff800000);
    float m0 = NEG, m1 = NEG, l0 = 0.f, l1 = 0.f;

    // staging: thread t covers row t>>2, halfword chunks (t&3)*2 and +1
    int srow = t >> 2, sch = (t & 3) * 2;
    unsigned ks_dst0 = su(&Ks[0][srow][0]);
    unsigned vs_dst0 = su(&Vs[0][srow][0]);
    const int SMEM_BUF = 64 * KVROW * 2;            // bytes per buffer

    // V ldsm per-lane base: row = l&15, halfword col = (l>>4)*8
    unsigned v_lm0 = su(&Vs[0][l & 15][(l >> 4) * 8]);

    // prologue: stage tile 0 into buffer 0
    {
        const __half* kg = Kb + (size_t)srow * D_ + sch * 8;
        const __half* vg = Vb + (size_t)srow * D_ + sch * 8;
        cp16(ks_dst0 + sch * 16, kg);
        cp16(ks_dst0 + sch * 16 + 16, kg + 8);
        cp16(vs_dst0 + sch * 16, vg);
        cp16(vs_dst0 + sch * 16 + 16, vg + 8);
        cp_commit();
    }

    int ntiles = (P_ + q0 + 128) / 64;
    for (int it = 0; it < ntiles; ++it) {
        int buf = it & 1;
        cp_wait<0>();
        __syncthreads();

        if (it + 1 < ntiles) {
            int jn = (it + 1) * 64;
            unsigned off = (buf ^ 1) ? SMEM_BUF : 0;
            const __half* kg = Kb + (size_t)(jn + srow) * D_ + sch * 8;
            const __half* vg = Vb + (size_t)(jn + srow) * D_ + sch * 8;
            cp16(ks_dst0 + off + sch * 16, kg);
            cp16(ks_dst0 + off + sch * 16 + 16, kg + 8);
            cp16(vs_dst0 + off + sch * 16, vg);
            cp16(vs_dst0 + off + sch * 16 + 16, vg + 8);
        }
        cp_commit();

        // scores
        float s[8][4];
#pragma unroll
        for (int nt = 0; nt < 8; nt++)
            s[nt][0] = s[nt][1] = s[nt][2] = s[nt][3] = 0.f;
#pragma unroll
        for (int kc = 0; kc < 4; kc++) {
#pragma unroll
            for (int nt = 0; nt < 8; nt++) {
                unsigned bf[2] = {
                    *(const unsigned*)&Ks[buf][nt * 8 + r][kc * 16 + 2 * c],
                    *(const unsigned*)&Ks[buf][nt * 8 + r][kc * 16 + 8 + 2 * c]
                };
                mma_f16(s[nt], qf[kc], bf);
            }
        }

        // scale + causal mask
        int j0 = it * 64;
        int qrow = q0 + w * 16 + r;
        int lim0 = P_ + qrow - j0;
        int lim1 = lim0 + 8;
#pragma unroll
        for (int nt = 0; nt < 8; nt++) {
            int j = nt * 8 + 2 * c;
            s[nt][0] = (j > lim0) ? NEG : s[nt][0] * SC;
            s[nt][1] = (j + 1 > lim0) ? NEG : s[nt][1] * SC;
            s[nt][2] = (j > lim1) ? NEG : s[nt][2] * SC;
            s[nt][3] = (j + 1 > lim1) ? NEG : s[nt][3] * SC;
        }

        // online softmax maxes
        float mx0 = NEG, mx1 = NEG;
#pragma unroll
        for (int nt = 0; nt < 8; nt++) {
            mx0 = fmaxf(mx0, fmaxf(s[nt][0], s[nt][1]));
            mx1 = fmaxf(mx1, fmaxf(s[nt][2], s[nt][3]));
        }
        mx0 = fmaxf(mx0, __shfl_xor_sync(0xffffffffu, mx0, 1));
        mx0 = fmaxf(mx0, __shfl_xor_sync(0xffffffffu, mx0, 2));
        mx1 = fmaxf(mx1, __shfl_xor_sync(0xffffffffu, mx1, 1));
        mx1 = fmaxf(mx1, __shfl_xor_sync(0xffffffffu, mx1, 2));
        float nm0 = fmaxf(m0, mx0), nm1 = fmaxf(m1, mx1);
        float a0 = ex2f(m0 - nm0), a1 = ex2f(m1 - nm1);
        m0 = nm0; m1 = nm1;
        l0 *= a0; l1 *= a1;
#pragma unroll
        for (int nt = 0; nt < 8; nt++) {
            o[nt][0] *= a0; o[nt][1] *= a0;
            o[nt][2] *= a1; o[nt][3] *= a1;
        }

        // P = 2^(s-m) in f16x2 (directly the PV A-fragment), PV mma via ldsm V
        unsigned vb = v_lm0 + (buf ? SMEM_BUF : 0);
#pragma unroll
        for (int ks = 0; ks < 4; ks++) {
            unsigned ap[4];
            ap[0] = h2exp(pack_f16(s[2 * ks][0] - nm0, s[2 * ks][1] - nm0));
            ap[1] = h2exp(pack_f16(s[2 * ks][2] - nm1, s[2 * ks][3] - nm1));
            ap[2] = h2exp(pack_f16(s[2 * ks + 1][0] - nm0, s[2 * ks + 1][1] - nm0));
            ap[3] = h2exp(pack_f16(s[2 * ks + 1][2] - nm1, s[2 * ks + 1][3] - nm1));
            float2 f0 = __half22float2(*(__half2*)&ap[0]);
            float2 f1 = __half22float2(*(__half2*)&ap[1]);
            float2 f2 = __half22float2(*(__half2*)&ap[2]);
            float2 f3 = __half22float2(*(__half2*)&ap[3]);
            l0 += f0.x + f0.y + f2.x + f2.y;
            l1 += f1.x + f1.y + f3.x + f3.y;
#pragma unroll
            for (int pair = 0; pair < 4; pair++) {
                unsigned v[4];
                ldsm_x4_trans(v, vb + ks * 16 * (KVROW * 2) + pair * 32);
                mma_f16(o[2 * pair], ap, v);
                mma_f16(o[2 * pair + 1], ap, v + 2);
            }
        }
        __syncthreads();
    }

    l0 += __shfl_xor_sync(0xffffffffu, l0, 1);
    l0 += __shfl_xor_sync(0xffffffffu, l0, 2);
    l1 += __shfl_xor_sync(0xffffffffu, l1, 1);
    l1 += __shfl_xor_sync(0xffffffffu, l1, 2);
    float inv0 = 1.f / l0, inv1 = 1.f / l1;

    int qrow = q0 + w * 16 + r;
    __half* dst0 = g_attn16 + ((size_t)(b * S_ + qrow)) * E_ + h * D_;
    __half* dst1 = dst0 + (size_t)8 * E_;
#pragma unroll
    for (int nt = 0; nt < 8; nt++) {
        int cc = nt * 8 + 2 * c;
        *(unsigned*)(dst0 + cc) = pack_f16(o[nt][0] * inv0, o[nt][1] * inv0);
        *(unsigned*)(dst1 + cc) = pack_f16(o[nt][2] * inv1, o[nt][3] * inv1);
    }
}

// ---------------------------------------------------------------------------
extern "C" void kernel_launch(void* const* d_in, const int* in_sizes, int n_in,
                              void* d_out, int out_size)
{
    (void)in_sizes; (void)n_in; (void)out_size;
    const float* x      = (const float*)d_in[0];
    const float* past   = (const float*)d_in[1];
    const float* w_attn = (const float*)d_in[2];
    const float* b_attn = (const float*)d_in[3];
    const float* w_proj = (const float*)d_in[4];
    const float* b_proj = (const float*)d_in[5];

    float* out     = (float*)d_out;
    float* present = out + (size_t)B_ * S_ * E_;

    convert_kernel<<<1024, 256>>>(x, w_attn, w_proj);
    gemm_f16_kernel<<<dim3(3 * E_ / 128 + 4, (B_ * S_) / 128), 256>>>(
        b_attn, nullptr, present, 3 * E_, 1, past);
    attn_mma_kernel<<<dim3(S_ / 128, B_ * H_), 256>>>();
    gemm_f16_kernel<<<dim3(E_ / 128, (B_ * S_) / 128), 256>>>(
        b_proj, out, nullptr, E_, 0, nullptr);
}

// round 14
// speedup vs baseline: 2.5073x; 1.1059x over previous
#include <cuda_runtime.h>
#include <cuda_fp16.h>

#define B_  4
#define S_  1024
#define H_  16
#define D_  64
#define E_  1024
#define P_  1024
#define NS_ 2048
#define K_  1024

__device__ __align__(16) __half g_x16[B_ * S_ * E_];
__device__ __align__(16) __half g_wa16[E_ * 3 * E_];
__device__ __align__(16) __half g_wp16[E_ * E_];
__device__ __align__(16) __half g_Qh16[B_ * H_ * S_ * D_];     // Q [B,H,S,D] f16
__device__ __align__(16) __half g_attn16[B_ * S_ * E_];        // attn out f16
__device__ __align__(16) __half g_kv16[2 * B_ * H_ * NS_ * D_]; // f16 mirror of present

// ---------------- helpers ----------------
__device__ __forceinline__ unsigned pack_f16(float lo, float hi) {
    unsigned r; asm("cvt.rn.f16x2.f32 %0, %1, %2;" : "=r"(r) : "f"(hi), "f"(lo)); return r;
}
__device__ __forceinline__ float ex2f(float x) {
    float r; asm("ex2.approx.ftz.f32 %0, %1;" : "=f"(r) : "f"(x)); return r;
}
__device__ __forceinline__ unsigned h2exp(unsigned x) {
    unsigned r; asm("ex2.approx.f16x2 %0, %1;" : "=r"(r) : "r"(x)); return r;
}
__device__ __forceinline__ void mma_f16(float* d, const unsigned* a, const unsigned* b) {
    asm volatile("mma.sync.aligned.m16n8k16.row.col.f32.f16.f16.f32 "
        "{%0,%1,%2,%3}, {%4,%5,%6,%7}, {%8,%9}, {%0,%1,%2,%3};"
        : "+f"(d[0]), "+f"(d[1]), "+f"(d[2]), "+f"(d[3])
        : "r"(a[0]), "r"(a[1]), "r"(a[2]), "r"(a[3]), "r"(b[0]), "r"(b[1]));
}
__device__ __forceinline__ unsigned su(const void* p) {
    return (unsigned)__cvta_generic_to_shared(p);
}
__device__ __forceinline__ void cp16(unsigned s, const void* g) {
    asm volatile("cp.async.ca.shared.global [%0], [%1], 16;" :: "r"(s), "l"(g));
}
__device__ __forceinline__ void cp_commit() {
    asm volatile("cp.async.commit_group;" ::: "memory");
}
template <int N> __device__ __forceinline__ void cp_wait() {
    asm volatile("cp.async.wait_group %0;" :: "n"(N) : "memory");
}
__device__ __forceinline__ void ldsm_x4(unsigned* d, unsigned addr) {
    asm volatile("ldmatrix.sync.aligned.m8n8.x4.shared.b16 {%0,%1,%2,%3}, [%4];"
        : "=r"(d[0]), "=r"(d[1]), "=r"(d[2]), "=r"(d[3]) : "r"(addr));
}
__device__ __forceinline__ void ldsm_x4_trans(unsigned* d, unsigned addr) {
    asm volatile("ldmatrix.sync.aligned.m8n8.x4.trans.shared.b16 {%0,%1,%2,%3}, [%4];"
        : "=r"(d[0]), "=r"(d[1]), "=r"(d[2]), "=r"(d[3]) : "r"(addr));
}

// ---------------- f32 -> f16 conversion (x, w_attn, w_proj) ----------------
__global__ __launch_bounds__(256) void convert_kernel(const float* __restrict__ x,
                                                      const float* __restrict__ wa,
                                                      const float* __restrict__ wp)
{
    const int NX4 = (B_ * S_ * E_) / 4;
    const int NWA4 = (E_ * 3 * E_) / 4;
    const int NWP4 = (E_ * E_) / 4;
    int gs = gridDim.x * blockDim.x;
    for (int i = blockIdx.x * blockDim.x + threadIdx.x; i < NX4 + NWA4 + NWP4; i += gs) {
        const float4* s; unsigned* d;
        if (i < NX4) { s = (const float4*)x + i; d = (unsigned*)g_x16 + i * 2; }
        else if (i < NX4 + NWA4) { int j = i - NX4; s = (const float4*)wa + j; d = (unsigned*)g_wa16 + j * 2; }
        else { int j = i - NX4 - NWA4; s = (const float4*)wp + j; d = (unsigned*)g_wp16 + j * 2; }
        float4 v = *s;
        d[0] = pack_f16(v.x, v.y);
        d[1] = pack_f16(v.z, v.w);
    }
}

// ---------------- pipelined f16 GEMM, 32k stages, ldmatrix both operands ----
#define AROW 40    // halfwords per A smem row (32 data + 8 pad = 80B)
#define BROW 136   // halfwords per B smem row (128 data + 8 pad = 272B)
#define ASTG (128 * AROW)
#define BSTG (32 * BROW)
__global__ __launch_bounds__(256) void gemm_f16_kernel(
    const float* __restrict__ bias, float* __restrict__ Cout,
    float* __restrict__ present, int N, int qkv_mode,
    const float* __restrict__ past)
{
    if (qkv_mode && (int)blockIdx.x >= (N >> 7)) {
        int part = ((int)blockIdx.x - (N >> 7)) * (int)gridDim.y + (int)blockIdx.y; // 0..127
        const float4* src = (const float4*)(past + (size_t)part * (P_ * D_));
        float4* dst = (float4*)(present + (size_t)part * (NS_ * D_));
        uint2* dst16 = (uint2*)(g_kv16 + (size_t)part * (NS_ * D_));
#pragma unroll 4
        for (int i = threadIdx.x; i < (P_ * D_) / 4; i += 256) {
            float4 v = src[i];
            dst[i] = v;
            dst16[i] = make_uint2(pack_f16(v.x, v.y), pack_f16(v.z, v.w));
        }
        return;
    }

    const __half* A = qkv_mode ? g_x16 : g_attn16;
    const __half* Bw = qkv_mode ? g_wa16 : g_wp16;

    __shared__ __align__(16) __half As[2][ASTG];
    __shared__ __align__(16) __half Bs[2][BSTG];

    int t = threadIdx.x;
    int bm = blockIdx.y * 128, bn = blockIdx.x * 128;
    int w = t >> 5, l = t & 31;
    int wm = (w & 1) * 64, wn = (w >> 1) * 32;
    int r = l >> 2, c = l & 3;

    float acc[4][4][4];
#pragma unroll
    for (int i = 0; i < 4; i++)
#pragma unroll
        for (int j = 0; j < 4; j++)
#pragma unroll
            for (int k = 0; k < 4; k++) acc[i][j][k] = 0.f;

    // staging: A thread t -> row t>>1, hw cols (t&1)*16 + {0,8}
    //          B thread t -> rows (t>>4), 16+(t>>4), hw col (t&15)*8
    int a_srow = t >> 1, a_scol = (t & 1) * 16;
    int b_srow = t >> 4, b_scol = (t & 15) * 8;
    const __half* Ag = A + (size_t)(bm + a_srow) * K_ + a_scol;
    const __half* Bg = Bw + (size_t)b_srow * N + bn + b_scol;
    unsigned a_dst = a_srow * AROW + a_scol;
    unsigned b_dst = b_srow * BROW + b_scol;

    // ldmatrix lane addressing
    int lm16 = l & 15, lmc = (l >> 4) * 8;

    // prologue: stage 0
    {
        cp16(su(&As[0][a_dst]), Ag);
        cp16(su(&As[0][a_dst + 8]), Ag + 8);
        cp16(su(&Bs[0][b_dst]), Bg);
        cp16(su(&Bs[0][b_dst + 16 * BROW]), Bg + (size_t)16 * N);
        cp_commit();
    }

    const int NIT = K_ / 32;   // 32
    for (int it = 0; it < NIT; ++it) {
        int buf = it & 1;
        cp_wait<0>();
        __syncthreads();

        if (it + 1 < NIT) {
            int nb = buf ^ 1, k0 = (it + 1) * 32;
            cp16(su(&As[nb][a_dst]), Ag + k0);
            cp16(su(&As[nb][a_dst + 8]), Ag + k0 + 8);
            cp16(su(&Bs[nb][b_dst]), Bg + (size_t)k0 * N);
            cp16(su(&Bs[nb][b_dst + 16 * BROW]), Bg + (size_t)(k0 + 16) * N);
        }
        cp_commit();

#pragma unroll
        for (int kk = 0; kk < 32; kk += 16) {
            unsigned af[4][4], bf[2][4];
#pragma unroll
            for (int mi = 0; mi < 4; mi++)
                ldsm_x4(af[mi], su(&As[buf][(wm + mi * 16 + lm16) * AROW + kk + lmc]));
            ldsm_x4_trans(bf[0], su(&Bs[buf][(kk + lm16) * BROW + wn + lmc]));
            ldsm_x4_trans(bf[1], su(&Bs[buf][(kk + lm16) * BROW + wn + lmc + 16]));
#pragma unroll
            for (int mi = 0; mi < 4; mi++)
#pragma unroll
                for (int ni = 0; ni < 4; ni++)
                    mma_f16(acc[mi][ni], af[mi], &bf[ni >> 1][(ni & 1) * 2]);
        }
    }

    // epilogue
#pragma unroll
    for (int mi = 0; mi < 4; mi++) {
#pragma unroll
        for (int ni = 0; ni < 4; ni++) {
            int row0 = bm + wm + mi * 16 + r;
            int col = bn + wn + ni * 8 + 2 * c;
#pragma unroll
            for (int half = 0; half < 2; half++) {
                int row = row0 + half * 8;
                float v0 = acc[mi][ni][half * 2 + 0] + bias[col];
                float v1 = acc[mi][ni][half * 2 + 1] + bias[col + 1];
                if (!qkv_mode) {
                    *(float2*)&Cout[(size_t)row * N + col] = make_float2(v0, v1);
                } else {
                    int b = row >> 10, s = row & 1023;
                    int part = col >> 10, nn = col & 1023;
                    int h = nn >> 6, d = nn & 63;
                    if (part == 0) {
                        *(unsigned*)&g_Qh16[(((size_t)(b * H_ + h) * S_) + s) * D_ + d] =
                            pack_f16(v0, v1);
                    } else {
                        int cbh = (part == 1) ? (b * H_ + h) : ((B_ + b) * H_ + h);
                        size_t idx = ((size_t)cbh * NS_ + P_ + s) * D_ + d;
                        *(float2*)&present[idx] = make_float2(v0, v1);
                        *(unsigned*)&g_kv16[idx] = pack_f16(v0, v1);
                    }
                }
            }
        }
    }
}

// ---------------- fp16 flash attention (unchanged from R12) ----------------
#define KVROW 72   // halfwords per smem row (64 data + 8 pad = 144B)
__global__ __launch_bounds__(256) void attn_mma_kernel()
{
    __shared__ __align__(16) __half Ks[2][64][KVROW];
    __shared__ __align__(16) __half Vs[2][64][KVROW];

    int t = threadIdx.x, w = t >> 5, l = t & 31;
    int r = l >> 2, c = l & 3;
    int bh = blockIdx.y, q0 = blockIdx.x * 128;
    int b = bh >> 4, h = bh & 15;

    const __half* Kb = g_kv16 + (size_t)bh * (NS_ * D_);
    const __half* Vb = g_kv16 + (size_t)(B_ * H_ + bh) * (NS_ * D_);

    const float SC = 0.125f * 1.4426950408889634f;
    unsigned qf[4][4];
    {
        const __half* Qp = g_Qh16 + ((size_t)bh * S_ + q0 + w * 16) * D_;
#pragma unroll
        for (int kc = 0; kc < 4; kc++) {
            int base = kc * 16;
            qf[kc][0] = *(const unsigned*)(Qp + (size_t)r * D_ + base + 2 * c);
            qf[kc][1] = *(const unsigned*)(Qp + (size_t)(r + 8) * D_ + base + 2 * c);
            qf[kc][2] = *(const unsigned*)(Qp + (size_t)r * D_ + base + 8 + 2 * c);
            qf[kc][3] = *(const unsigned*)(Qp + (size_t)(r + 8) * D_ + base + 8 + 2 * c);
        }
    }

    float o[8][4];
#pragma unroll
    for (int i = 0; i < 8; i++)
#pragma unroll
        for (int j = 0; j < 4; j++) o[i][j] = 0.f;
    const float NEG = __int_as_float(0xff800000);
    float m0 = NEG, m1 = NEG, l0 = 0.f, l1 = 0.f;

    int srow = t >> 2, sch = (t & 3) * 2;
    unsigned ks_dst0 = su(&Ks[0][srow][0]);
    unsigned vs_dst0 = su(&Vs[0][srow][0]);
    const int SMEM_BUF = 64 * KVROW * 2;

    unsigned v_lm0 = su(&Vs[0][l & 15][(l >> 4) * 8]);

    {
        const __half* kg = Kb + (size_t)srow * D_ + sch * 8;
        const __half* vg = Vb + (size_t)srow * D_ + sch * 8;
        cp16(ks_dst0 + sch * 16, kg);
        cp16(ks_dst0 + sch * 16 + 16, kg + 8);
        cp16(vs_dst0 + sch * 16, vg);
        cp16(vs_dst0 + sch * 16 + 16, vg + 8);
        cp_commit();
    }

    int ntiles = (P_ + q0 + 128) / 64;
    for (int it = 0; it < ntiles; ++it) {
        int buf = it & 1;
        cp_wait<0>();
        __syncthreads();

        if (it + 1 < ntiles) {
            int jn = (it + 1) * 64;
            unsigned off = (buf ^ 1) ? SMEM_BUF : 0;
            const __half* kg = Kb + (size_t)(jn + srow) * D_ + sch * 8;
            const __half* vg = Vb + (size_t)(jn + srow) * D_ + sch * 8;
            cp16(ks_dst0 + off + sch * 16, kg);
            cp16(ks_dst0 + off + sch * 16 + 16, kg + 8);
            cp16(vs_dst0 + off + sch * 16, vg);
            cp16(vs_dst0 + off + sch * 16 + 16, vg + 8);
        }
        cp_commit();

        float s[8][4];
#pragma unroll
        for (int nt = 0; nt < 8; nt++)
            s[nt][0] = s[nt][1] = s[nt][2] = s[nt][3] = 0.f;
#pragma unroll
        for (int kc = 0; kc < 4; kc++) {
#pragma unroll
            for (int nt = 0; nt < 8; nt++) {
                unsigned bf[2] = {
                    *(const unsigned*)&Ks[buf][nt * 8 + r][kc * 16 + 2 * c],
                    *(const unsigned*)&Ks[buf][nt * 8 + r][kc * 16 + 8 + 2 * c]
                };
                mma_f16(s[nt], qf[kc], bf);
            }
        }

        int j0 = it * 64;
        int qrow = q0 + w * 16 + r;
        int lim0 = P_ + qrow - j0;
        int lim1 = lim0 + 8;
#pragma unroll
        for (int nt = 0; nt < 8; nt++) {
            int j = nt * 8 + 2 * c;
            s[nt][0] = (j > lim0) ? NEG : s[nt][0] * SC;
            s[nt][1] = (j + 1 > lim0) ? NEG : s[nt][1] * SC;
            s[nt][2] = (j > lim1) ? NEG : s[nt][2] * SC;
            s[nt][3] = (j + 1 > lim1) ? NEG : s[nt][3] * SC;
        }

        float mx0 = NEG, mx1 = NEG;
#pragma unroll
        for (int nt = 0; nt < 8; nt++) {
            mx0 = fmaxf(mx0, fmaxf(s[nt][0], s[nt][1]));
            mx1 = fmaxf(mx1, fmaxf(s[nt][2], s[nt][3]));
        }
        mx0 = fmaxf(mx0, __shfl_xor_sync(0xffffffffu, mx0, 1));
        mx0 = fmaxf(mx0, __shfl_xor_sync(0xffffffffu, mx0, 2));
        mx1 = fmaxf(mx1, __shfl_xor_sync(0xffffffffu, mx1, 1));
        mx1 = fmaxf(mx1, __shfl_xor_sync(0xffffffffu, mx1, 2));
        float nm0 = fmaxf(m0, mx0), nm1 = fmaxf(m1, mx1);
        float a0 = ex2f(m0 - nm0), a1 = ex2f(m1 - nm1);
        m0 = nm0; m1 = nm1;
        l0 *= a0; l1 *= a1;
#pragma unroll
        for (int nt = 0; nt < 8; nt++) {
            o[nt][0] *= a0; o[nt][1] *= a0;
            o[nt][2] *= a1; o[nt][3] *= a1;
        }

        unsigned vb = v_lm0 + (buf ? SMEM_BUF : 0);
#pragma unroll
        for (int ks = 0; ks < 4; ks++) {
            unsigned ap[4];
            ap[0] = h2exp(pack_f16(s[2 * ks][0] - nm0, s[2 * ks][1] - nm0));
            ap[1] = h2exp(pack_f16(s[2 * ks][2] - nm1, s[2 * ks][3] - nm1));
            ap[2] = h2exp(pack_f16(s[2 * ks + 1][0] - nm0, s[2 * ks + 1][1] - nm0));
            ap[3] = h2exp(pack_f16(s[2 * ks + 1][2] - nm1, s[2 * ks + 1][3] - nm1));
            float2 f0 = __half22float2(*(__half2*)&ap[0]);
            float2 f1 = __half22float2(*(__half2*)&ap[1]);
            float2 f2 = __half22float2(*(__half2*)&ap[2]);
            float2 f3 = __half22float2(*(__half2*)&ap[3]);
            l0 += f0.x + f0.y + f2.x + f2.y;
            l1 += f1.x + f1.y + f3.x + f3.y;
#pragma unroll
            for (int pair = 0; pair < 4; pair++) {
                unsigned v[4];
                ldsm_x4_trans(v, vb + ks * 16 * (KVROW * 2) + pair * 32);
                mma_f16(o[2 * pair], ap, v);
                mma_f16(o[2 * pair + 1], ap, v + 2);
            }
        }
        __syncthreads();
    }

    l0 += __shfl_xor_sync(0xffffffffu, l0, 1);
    l0 += __shfl_xor_sync(0xffffffffu, l0, 2);
    l1 += __shfl_xor_sync(0xffffffffu, l1, 1);
    l1 += __shfl_xor_sync(0xffffffffu, l1, 2);
    float inv0 = 1.f / l0, inv1 = 1.f / l1;

    int qrow = q0 + w * 16 + r;
    __half* dst0 = g_attn16 + ((size_t)(b * S_ + qrow)) * E_ + h * D_;
    __half* dst1 = dst0 + (size_t)8 * E_;
#pragma unroll
    for (int nt = 0; nt < 8; nt++) {
        int cc = nt * 8 + 2 * c;
        *(unsigned*)(dst0 + cc) = pack_f16(o[nt][0] * inv0, o[nt][1] * inv0);
        *(unsigned*)(dst1 + cc) = pack_f16(o[nt][2] * inv1, o[nt][3] * inv1);
    }
}

// ---------------------------------------------------------------------------
extern "C" void kernel_launch(void* const* d_in, const int* in_sizes, int n_in,
                              void* d_out, int out_size)
{
    (void)in_sizes; (void)n_in; (void)out_size;
    const float* x      = (const float*)d_in[0];
    const float* past   = (const float*)d_in[1];
    const float* w_attn = (const float*)d_in[2];
    const float* b_attn = (const float*)d_in[3];
    const float* w_proj = (const float*)d_in[4];
    const float* b_proj = (const float*)d_in[5];

    float* out     = (float*)d_out;
    float* present = out + (size_t)B_ * S_ * E_;

    convert_kernel<<<1024, 256>>>(x, w_attn, w_proj);
    gemm_f16_kernel<<<dim3(3 * E_ / 128 + 4, (B_ * S_) / 128), 256>>>(
        b_attn, nullptr, present, 3 * E_, 1, past);
    attn_mma_kernel<<<dim3(S_ / 128, B_ * H_), 256>>>();
    gemm_f16_kernel<<<dim3(E_ / 128, (B_ * S_) / 128), 256>>>(
        b_proj, out, nullptr, E_, 0, nullptr);
}